// round 1
// baseline (speedup 1.0000x reference)
#include <cuda_runtime.h>
#include <math.h>

// ---------------------------------------------------------------------------
// VAE forward: enc(27648->900->300) -> logvar(16) -> triangular latent solve
// -> dec(16->300->300->27648). Outputs concatenated: z, logvar, Bz, Bmat, xhat.
// Round 1: correct fp32 baseline with a generic tiled SGEMM (fused bias+act).
// ---------------------------------------------------------------------------

#define BATCH 1024
#define IMG   27648
#define H1    900
#define H2    300
#define D     16

#define BM 64
#define BN 64
#define BK 16

enum { ACT_NONE = 0, ACT_ELU = 1, ACT_TANH = 2 };

// Scratch (no allocation allowed anywhere -> __device__ globals).
__device__ float g_h1[BATCH * H1];
__device__ float g_h2[BATCH * H2];
__device__ float g_g1[BATCH * H2];
__device__ float g_g2[BATCH * H2];

// Generic tiled SGEMM: C[M,N] = act(A[M,K] @ B[K,N] + bias[N])
template <int ACT>
__global__ void __launch_bounds__(256)
gemm_bias_act(const float* __restrict__ A, const float* __restrict__ B,
              const float* __restrict__ bias, float* __restrict__ C,
              int M, int N, int K)
{
    __shared__ float As[BK][BM + 1];   // +1 pad: conflict-free transposed stores
    __shared__ float Bs[BK][BN];

    const int t  = threadIdx.x;
    const int tx = t & 15;             // 16 col-threads
    const int ty = t >> 4;             // 16 row-threads
    const int n0 = blockIdx.x * BN;
    const int m0 = blockIdx.y * BM;

    float acc[4][4];
#pragma unroll
    for (int i = 0; i < 4; i++)
#pragma unroll
        for (int j = 0; j < 4; j++) acc[i][j] = 0.f;

    for (int k0 = 0; k0 < K; k0 += BK) {
        // A tile: 64 rows x 16 k (coalesced in k), stored transposed.
#pragma unroll
        for (int i = 0; i < 4; i++) {
            int e = t + i * 256;
            int c = e & 15;            // k within tile
            int r = e >> 4;            // m within tile
            int gm = m0 + r, gk = k0 + c;
            As[c][r] = (gm < M && gk < K) ? A[(size_t)gm * K + gk] : 0.f;
        }
        // B tile: 16 k x 64 n (coalesced in n).
#pragma unroll
        for (int i = 0; i < 4; i++) {
            int e = t + i * 256;
            int n = e & 63;
            int kk = e >> 6;
            int gk = k0 + kk, gn = n0 + n;
            Bs[kk][n] = (gk < K && gn < N) ? B[(size_t)gk * N + gn] : 0.f;
        }
        __syncthreads();

#pragma unroll
        for (int k = 0; k < BK; k++) {
            float a[4], b[4];
#pragma unroll
            for (int i = 0; i < 4; i++) a[i] = As[k][ty * 4 + i];
#pragma unroll
            for (int j = 0; j < 4; j++) b[j] = Bs[k][tx * 4 + j];
#pragma unroll
            for (int i = 0; i < 4; i++)
#pragma unroll
                for (int j = 0; j < 4; j++)
                    acc[i][j] = fmaf(a[i], b[j], acc[i][j]);
        }
        __syncthreads();
    }

#pragma unroll
    for (int i = 0; i < 4; i++) {
        int gm = m0 + ty * 4 + i;
        if (gm >= M) continue;
#pragma unroll
        for (int j = 0; j < 4; j++) {
            int gn = n0 + tx * 4 + j;
            if (gn >= N) continue;
            float v = acc[i][j] + bias[gn];
            if (ACT == ACT_ELU)  v = (v > 0.f) ? v : expm1f(v);
            if (ACT == ACT_TANH) v = tanhf(v);
            C[(size_t)gm * N + gn] = v;
        }
    }
}

// Bmat[i,j] = W[i,j] * max(j - i, 0)   (value j-i, strictly upper triangular)
__global__ void bmat_kernel(const float* __restrict__ W, float* __restrict__ bmat)
{
    int t = threadIdx.x;               // 256 threads == 16x16
    int i = t >> 4, j = t & 15;
    bmat[t] = (j > i) ? W[t] * (float)(j - i) : 0.f;
}

// Per-row d=16 forward substitution:
//   eps_j = exp(logvar_j/2) * noise_j
//   s_j   = sum_{i<j} z_i * B[i,j]   -> Bz
//   z_j   = eps_j + s_j              -> z
__global__ void z_kernel(const float* __restrict__ W,
                         const float* __restrict__ logvar,
                         const float* __restrict__ noise,
                         float* __restrict__ z_out,
                         float* __restrict__ bz_out)
{
    __shared__ float sB[D][D];
    int t = threadIdx.x;
    {
        int i = t >> 4, j = t & 15;
        sB[i][j] = (j > i) ? W[t] * (float)(j - i) : 0.f;
    }
    __syncthreads();

    int b = blockIdx.x * 256 + t;
    float eps[D], zz[D], bz[D];
#pragma unroll
    for (int j = 0; j < D; j++)
        eps[j] = expf(0.5f * logvar[b * D + j]) * noise[b * D + j];
#pragma unroll
    for (int j = 0; j < D; j++) {
        float s = 0.f;
#pragma unroll
        for (int i = 0; i < D; i++)
            if (i < j) s = fmaf(zz[i], sB[i][j], s);
        bz[j] = s;
        zz[j] = eps[j] + s;
    }
#pragma unroll
    for (int j = 0; j < D; j++) {
        z_out[b * D + j]  = zz[j];
        bz_out[b * D + j] = bz[j];
    }
}

extern "C" void kernel_launch(void* const* d_in, const int* in_sizes, int n_in,
                              void* d_out, int out_size)
{
    (void)in_sizes; (void)n_in; (void)out_size;

    const float* x        = (const float*)d_in[0];
    const float* noise    = (const float*)d_in[1];
    const float* enc_w1   = (const float*)d_in[2];
    const float* enc_b1   = (const float*)d_in[3];
    const float* enc_w2   = (const float*)d_in[4];
    const float* enc_b2   = (const float*)d_in[5];
    const float* logvar_w = (const float*)d_in[6];
    const float* logvar_b = (const float*)d_in[7];
    const float* W        = (const float*)d_in[8];
    const float* dec_w1   = (const float*)d_in[9];
    const float* dec_b1   = (const float*)d_in[10];
    const float* dec_w2   = (const float*)d_in[11];
    const float* dec_b2   = (const float*)d_in[12];
    const float* dec_w3   = (const float*)d_in[13];
    const float* dec_b3   = (const float*)d_in[14];

    float* out  = (float*)d_out;
    float* z_o  = out;                                // [1024,16]
    float* lv_o = out + BATCH * D;                    // [1024,16]
    float* bz_o = out + 2 * BATCH * D;                // [1024,16]
    float* bm_o = out + 3 * BATCH * D;                // [16,16]
    float* xh_o = out + 3 * BATCH * D + D * D;        // [1024,27648]

    float *h1, *h2, *g1, *g2;
    cudaGetSymbolAddress((void**)&h1, g_h1);
    cudaGetSymbolAddress((void**)&h2, g_h2);
    cudaGetSymbolAddress((void**)&g1, g_g1);
    cudaGetSymbolAddress((void**)&g2, g_g2);

    dim3 blk(256);

    // encoder
    gemm_bias_act<ACT_ELU ><<<dim3((H1  + BN - 1) / BN, BATCH / BM), blk>>>(
        x,  enc_w1, enc_b1, h1, BATCH, H1, IMG);
    gemm_bias_act<ACT_ELU ><<<dim3((H2  + BN - 1) / BN, BATCH / BM), blk>>>(
        h1, enc_w2, enc_b2, h2, BATCH, H2, H1);
    gemm_bias_act<ACT_NONE><<<dim3((D   + BN - 1) / BN, BATCH / BM), blk>>>(
        h2, logvar_w, logvar_b, lv_o, BATCH, D, H2);

    // latent
    bmat_kernel<<<1, 256>>>(W, bm_o);
    z_kernel<<<BATCH / 256, 256>>>(W, lv_o, noise, z_o, bz_o);

    // decoder
    gemm_bias_act<ACT_ELU ><<<dim3((H2  + BN - 1) / BN, BATCH / BM), blk>>>(
        z_o, dec_w1, dec_b1, g1, BATCH, H2, D);
    gemm_bias_act<ACT_ELU ><<<dim3((H2  + BN - 1) / BN, BATCH / BM), blk>>>(
        g1, dec_w2, dec_b2, g2, BATCH, H2, H2);
    gemm_bias_act<ACT_TANH><<<dim3((IMG + BN - 1) / BN, BATCH / BM), blk>>>(
        g2, dec_w3, dec_b3, xh_o, BATCH, IMG, H2);
}

// round 2
// speedup vs baseline: 2.2493x; 2.2493x over previous
#include <cuda_runtime.h>
#include <cuda_bf16.h>
#include <math.h>
#include <stdint.h>

// ---------------------------------------------------------------------------
// VAE forward. Round 2: enc1 and dec3 GEMMs on tensor cores via bf16 hi/lo
// 3-product split (fp32-class accuracy), mma.sync.m16n8k16 + cp.async pipeline.
// Small GEMMs stay fp32 SIMT.
// ---------------------------------------------------------------------------

#define BATCH 1024
#define IMG   27648
#define H1    900
#define H2    300
#define D     16

enum { ACT_NONE = 0, ACT_ELU = 1, ACT_TANH = 2 };

// ---------------- scratch (__device__ globals; no allocs allowed) ----------
__device__ float g_h1[BATCH * H1];
__device__ float g_h2[BATCH * H2];
__device__ float g_g1[BATCH * H2];
__device__ float g_g2[BATCH * H2];

// bf16 split buffers (padded shapes)
#define W1N_PAD 960          // 900 -> 15*64
#define W3K_PAD 320          // 300 -> 10*32
__device__ __nv_bfloat16 g_xh[BATCH * IMG];
__device__ __nv_bfloat16 g_xl[BATCH * IMG];
__device__ __nv_bfloat16 g_w1h[IMG * W1N_PAD];
__device__ __nv_bfloat16 g_w1l[IMG * W1N_PAD];
__device__ __nv_bfloat16 g_w3h[W3K_PAD * IMG];
__device__ __nv_bfloat16 g_w3l[W3K_PAD * IMG];
__device__ __nv_bfloat16 g_g2h[BATCH * W3K_PAD];
__device__ __nv_bfloat16 g_g2l[BATCH * W3K_PAD];

// ---------------- fp32 -> (hi, lo) bf16 split with zero padding ------------
__global__ void split_bf16(const float* __restrict__ src,
                           __nv_bfloat16* __restrict__ hi,
                           __nv_bfloat16* __restrict__ lo,
                           int src_rows, int src_cols, int dst_cols)
{
    int c = blockIdx.x * 256 + threadIdx.x;
    int r = blockIdx.y;
    if (c >= dst_cols) return;
    float v = (r < src_rows && c < src_cols) ? src[(size_t)r * src_cols + c] : 0.f;
    __nv_bfloat16 h = __float2bfloat16_rn(v);
    float rem = v - __bfloat162float(h);
    size_t o = (size_t)r * dst_cols + c;
    hi[o] = h;
    lo[o] = __float2bfloat16_rn(rem);
}

// ---------------- tensor-core GEMM (bf16x3 split) ---------------------------
// C[M,N] = act(Ah@Bh + Ah@Bl + Al@Bh + bias), A row-major [M,K], B [K,N].
// BM=128, BN=64, BK=32, 256 threads (8 warps, 32x32 warp tiles).

#define BM 128
#define BN 64
#define BK 32
#define ASTR 40   // bf16 row stride for A smem (conflict-free ldmatrix)
#define BSTR 72   // bf16 row stride for B smem

#define A_BYTES (BM * ASTR * 2)   // 10240
#define B_BYTES (BK * BSTR * 2)   // 4608
#define STAGE_BYTES (2 * A_BYTES + 2 * B_BYTES)   // 29696
#define SMEM_BYTES (2 * STAGE_BYTES)              // 59392

__device__ __forceinline__ void cp16(void* s, const void* g)
{
    uint32_t sa = (uint32_t)__cvta_generic_to_shared(s);
    asm volatile("cp.async.cg.shared.global [%0], [%1], 16;\n" :: "r"(sa), "l"(g));
}

__device__ __forceinline__ void ldsm_x4(uint32_t* r, const void* p)
{
    uint32_t a = (uint32_t)__cvta_generic_to_shared(p);
    asm volatile("ldmatrix.sync.aligned.m8n8.x4.shared.b16 {%0,%1,%2,%3}, [%4];\n"
                 : "=r"(r[0]), "=r"(r[1]), "=r"(r[2]), "=r"(r[3]) : "r"(a));
}

__device__ __forceinline__ void ldsm_x4_t(uint32_t* r, const void* p)
{
    uint32_t a = (uint32_t)__cvta_generic_to_shared(p);
    asm volatile("ldmatrix.sync.aligned.m8n8.x4.trans.shared.b16 {%0,%1,%2,%3}, [%4];\n"
                 : "=r"(r[0]), "=r"(r[1]), "=r"(r[2]), "=r"(r[3]) : "r"(a));
}

__device__ __forceinline__ void mma16816(float* c, const uint32_t* a, const uint32_t* b)
{
    asm volatile(
        "mma.sync.aligned.m16n8k16.row.col.f32.bf16.bf16.f32 "
        "{%0,%1,%2,%3}, {%4,%5,%6,%7}, {%8,%9}, {%0,%1,%2,%3};\n"
        : "+f"(c[0]), "+f"(c[1]), "+f"(c[2]), "+f"(c[3])
        : "r"(a[0]), "r"(a[1]), "r"(a[2]), "r"(a[3]), "r"(b[0]), "r"(b[1]));
}

template <int ACT>
__global__ void __launch_bounds__(256)
mma_gemm_split(const __nv_bfloat16* __restrict__ Ah, const __nv_bfloat16* __restrict__ Al,
               int lda,
               const __nv_bfloat16* __restrict__ Bh, const __nv_bfloat16* __restrict__ Bl,
               int ldb,
               const float* __restrict__ bias, float* __restrict__ C, int ldc,
               int N, int KT)
{
    extern __shared__ char smem[];
    __nv_bfloat16* sAh[2];
    __nv_bfloat16* sAl[2];
    __nv_bfloat16* sBh[2];
    __nv_bfloat16* sBl[2];
#pragma unroll
    for (int s = 0; s < 2; s++) {
        char* base = smem + s * STAGE_BYTES;
        sAh[s] = (__nv_bfloat16*)(base);
        sAl[s] = (__nv_bfloat16*)(base + A_BYTES);
        sBh[s] = (__nv_bfloat16*)(base + 2 * A_BYTES);
        sBl[s] = (__nv_bfloat16*)(base + 2 * A_BYTES + B_BYTES);
    }

    const int t    = threadIdx.x;
    const int lane = t & 31;
    const int wid  = t >> 5;
    const int wm   = wid & 3;       // 4 warps over M (32 rows each)
    const int wn   = wid >> 2;      // 2 warps over N (32 cols each)
    const int m0   = blockIdx.y * BM;
    const int n0   = blockIdx.x * BN;

    float acc[2][4][4];
#pragma unroll
    for (int i = 0; i < 2; i++)
#pragma unroll
        for (int j = 0; j < 4; j++)
#pragma unroll
            for (int q = 0; q < 4; q++) acc[i][j][q] = 0.f;

    // tile loader: 16B chunks via cp.async
    auto load_stage = [&](int s, int kt) {
        const int k0 = kt * BK;
#pragma unroll
        for (int i = 0; i < 2; i++) {
            int c   = t + i * 256;          // 0..511
            int row = c >> 2;               // 0..127
            int seg = (c & 3) << 3;         // 0,8,16,24
            size_t go = (size_t)(m0 + row) * lda + k0 + seg;
            int    so = row * ASTR + seg;
            cp16(&sAh[s][so], &Ah[go]);
            cp16(&sAl[s][so], &Al[go]);
        }
        {
            int row = t >> 3;               // 0..31
            int seg = (t & 7) << 3;         // 0..56
            size_t go = (size_t)(k0 + row) * ldb + n0 + seg;
            int    so = row * BSTR + seg;
            cp16(&sBh[s][so], &Bh[go]);
            cp16(&sBl[s][so], &Bl[go]);
        }
        asm volatile("cp.async.commit_group;\n");
    };

    load_stage(0, 0);
    int s = 0;

    for (int kt = 0; kt < KT; kt++) {
        if (kt + 1 < KT) {
            load_stage(s ^ 1, kt + 1);
            asm volatile("cp.async.wait_group 1;\n");
        } else {
            asm volatile("cp.async.wait_group 0;\n");
        }
        __syncthreads();

#pragma unroll
        for (int ks = 0; ks < 2; ks++) {   // two k16 steps per BK=32
            uint32_t afh[2][4], afl[2][4];
#pragma unroll
            for (int mt = 0; mt < 2; mt++) {
                int r = wm * 32 + mt * 16 + (lane & 15);
                int c = ks * 16 + ((lane >> 4) << 3);
                ldsm_x4(afh[mt], &sAh[s][r * ASTR + c]);
                ldsm_x4(afl[mt], &sAl[s][r * ASTR + c]);
            }
            uint32_t bfh[4][2], bfl[4][2];
#pragma unroll
            for (int np = 0; np < 2; np++) {
                int r = ks * 16 + (lane & 15);
                int c = wn * 32 + np * 16 + ((lane >> 4) << 3);
                uint32_t rh[4], rl[4];
                ldsm_x4_t(rh, &sBh[s][r * BSTR + c]);
                ldsm_x4_t(rl, &sBl[s][r * BSTR + c]);
                bfh[np * 2][0] = rh[0]; bfh[np * 2][1] = rh[1];
                bfh[np * 2 + 1][0] = rh[2]; bfh[np * 2 + 1][1] = rh[3];
                bfl[np * 2][0] = rl[0]; bfl[np * 2][1] = rl[1];
                bfl[np * 2 + 1][0] = rl[2]; bfl[np * 2 + 1][1] = rl[3];
            }
#pragma unroll
            for (int mt = 0; mt < 2; mt++)
#pragma unroll
                for (int nt = 0; nt < 4; nt++) {
                    mma16816(acc[mt][nt], afh[mt], bfh[nt]);
                    mma16816(acc[mt][nt], afh[mt], bfl[nt]);
                    mma16816(acc[mt][nt], afl[mt], bfh[nt]);
                }
        }
        __syncthreads();
        s ^= 1;
    }

    // epilogue: bias + act + store
#pragma unroll
    for (int mt = 0; mt < 2; mt++) {
#pragma unroll
        for (int nt = 0; nt < 4; nt++) {
            int col = n0 + wn * 32 + nt * 8 + (lane & 3) * 2;
            if (col >= N) continue;
            float b0 = bias[col];
            float b1 = (col + 1 < N) ? bias[col + 1] : 0.f;
#pragma unroll
            for (int h = 0; h < 2; h++) {   // row halves (+0, +8)
                int row = m0 + wm * 32 + mt * 16 + (lane >> 2) + h * 8;
                float v0 = acc[mt][nt][2 * h + 0] + b0;
                float v1 = acc[mt][nt][2 * h + 1] + b1;
                if (ACT == ACT_ELU)  { v0 = v0 > 0.f ? v0 : expm1f(v0);
                                       v1 = v1 > 0.f ? v1 : expm1f(v1); }
                if (ACT == ACT_TANH) { v0 = tanhf(v0); v1 = tanhf(v1); }
                if (col + 1 < N) {
                    *(float2*)&C[(size_t)row * ldc + col] = make_float2(v0, v1);
                } else {
                    C[(size_t)row * ldc + col] = v0;
                }
            }
        }
    }
}

// ---------------- fp32 SIMT GEMM for the small layers ----------------------
#define SBM 64
#define SBN 64
#define SBK 16

template <int ACT>
__global__ void __launch_bounds__(256)
gemm_bias_act(const float* __restrict__ A, const float* __restrict__ B,
              const float* __restrict__ bias, float* __restrict__ C,
              int M, int N, int K)
{
    __shared__ float As[SBK][SBM + 1];
    __shared__ float Bs[SBK][SBN];

    const int t  = threadIdx.x;
    const int tx = t & 15;
    const int ty = t >> 4;
    const int n0 = blockIdx.x * SBN;
    const int m0 = blockIdx.y * SBM;

    float acc[4][4];
#pragma unroll
    for (int i = 0; i < 4; i++)
#pragma unroll
        for (int j = 0; j < 4; j++) acc[i][j] = 0.f;

    for (int k0 = 0; k0 < K; k0 += SBK) {
#pragma unroll
        for (int i = 0; i < 4; i++) {
            int e = t + i * 256;
            int c = e & 15, r = e >> 4;
            int gm = m0 + r, gk = k0 + c;
            As[c][r] = (gm < M && gk < K) ? A[(size_t)gm * K + gk] : 0.f;
        }
#pragma unroll
        for (int i = 0; i < 4; i++) {
            int e = t + i * 256;
            int n = e & 63, kk = e >> 6;
            int gk = k0 + kk, gn = n0 + n;
            Bs[kk][n] = (gk < K && gn < N) ? B[(size_t)gk * N + gn] : 0.f;
        }
        __syncthreads();
#pragma unroll
        for (int k = 0; k < SBK; k++) {
            float a[4], b[4];
#pragma unroll
            for (int i = 0; i < 4; i++) a[i] = As[k][ty * 4 + i];
#pragma unroll
            for (int j = 0; j < 4; j++) b[j] = Bs[k][tx * 4 + j];
#pragma unroll
            for (int i = 0; i < 4; i++)
#pragma unroll
                for (int j = 0; j < 4; j++)
                    acc[i][j] = fmaf(a[i], b[j], acc[i][j]);
        }
        __syncthreads();
    }

#pragma unroll
    for (int i = 0; i < 4; i++) {
        int gm = m0 + ty * 4 + i;
        if (gm >= M) continue;
#pragma unroll
        for (int j = 0; j < 4; j++) {
            int gn = n0 + tx * 4 + j;
            if (gn >= N) continue;
            float v = acc[i][j] + bias[gn];
            if (ACT == ACT_ELU)  v = (v > 0.f) ? v : expm1f(v);
            if (ACT == ACT_TANH) v = tanhf(v);
            C[(size_t)gm * N + gn] = v;
        }
    }
}

// ---------------- latent path ----------------------------------------------
__global__ void bmat_kernel(const float* __restrict__ W, float* __restrict__ bmat)
{
    int t = threadIdx.x;
    int i = t >> 4, j = t & 15;
    bmat[t] = (j > i) ? W[t] * (float)(j - i) : 0.f;
}

__global__ void z_kernel(const float* __restrict__ W,
                         const float* __restrict__ logvar,
                         const float* __restrict__ noise,
                         float* __restrict__ z_out,
                         float* __restrict__ bz_out)
{
    __shared__ float sB[D][D];
    int t = threadIdx.x;
    {
        int i = t >> 4, j = t & 15;
        sB[i][j] = (j > i) ? W[t] * (float)(j - i) : 0.f;
    }
    __syncthreads();

    int b = blockIdx.x * 256 + t;
    float eps[D], zz[D], bz[D];
#pragma unroll
    for (int j = 0; j < D; j++)
        eps[j] = expf(0.5f * logvar[b * D + j]) * noise[b * D + j];
#pragma unroll
    for (int j = 0; j < D; j++) {
        float sum = 0.f;
#pragma unroll
        for (int i = 0; i < D; i++)
            if (i < j) sum = fmaf(zz[i], sB[i][j], sum);
        bz[j] = sum;
        zz[j] = eps[j] + sum;
    }
#pragma unroll
    for (int j = 0; j < D; j++) {
        z_out[b * D + j]  = zz[j];
        bz_out[b * D + j] = bz[j];
    }
}

// ---------------- launch -----------------------------------------------------
extern "C" void kernel_launch(void* const* d_in, const int* in_sizes, int n_in,
                              void* d_out, int out_size)
{
    (void)in_sizes; (void)n_in; (void)out_size;

    const float* x        = (const float*)d_in[0];
    const float* noise    = (const float*)d_in[1];
    const float* enc_w1   = (const float*)d_in[2];
    const float* enc_b1   = (const float*)d_in[3];
    const float* enc_w2   = (const float*)d_in[4];
    const float* enc_b2   = (const float*)d_in[5];
    const float* logvar_w = (const float*)d_in[6];
    const float* logvar_b = (const float*)d_in[7];
    const float* W        = (const float*)d_in[8];
    const float* dec_w1   = (const float*)d_in[9];
    const float* dec_b1   = (const float*)d_in[10];
    const float* dec_w2   = (const float*)d_in[11];
    const float* dec_b2   = (const float*)d_in[12];
    const float* dec_w3   = (const float*)d_in[13];
    const float* dec_b3   = (const float*)d_in[14];

    float* out  = (float*)d_out;
    float* z_o  = out;
    float* lv_o = out + BATCH * D;
    float* bz_o = out + 2 * BATCH * D;
    float* bm_o = out + 3 * BATCH * D;
    float* xh_o = out + 3 * BATCH * D + D * D;

    float *h1, *h2, *g1, *g2;
    cudaGetSymbolAddress((void**)&h1, g_h1);
    cudaGetSymbolAddress((void**)&h2, g_h2);
    cudaGetSymbolAddress((void**)&g1, g_g1);
    cudaGetSymbolAddress((void**)&g2, g_g2);
    __nv_bfloat16 *xh, *xl, *w1h, *w1l, *w3h, *w3l, *g2h, *g2l;
    cudaGetSymbolAddress((void**)&xh,  g_xh);
    cudaGetSymbolAddress((void**)&xl,  g_xl);
    cudaGetSymbolAddress((void**)&w1h, g_w1h);
    cudaGetSymbolAddress((void**)&w1l, g_w1l);
    cudaGetSymbolAddress((void**)&w3h, g_w3h);
    cudaGetSymbolAddress((void**)&w3l, g_w3l);
    cudaGetSymbolAddress((void**)&g2h, g_g2h);
    cudaGetSymbolAddress((void**)&g2l, g_g2l);

    // opt-in smem for the mma kernels (>48KB)
    cudaFuncSetAttribute(mma_gemm_split<ACT_ELU>,
                         cudaFuncAttributeMaxDynamicSharedMemorySize, SMEM_BYTES);
    cudaFuncSetAttribute(mma_gemm_split<ACT_TANH>,
                         cudaFuncAttributeMaxDynamicSharedMemorySize, SMEM_BYTES);

    dim3 blk(256);

    // ---- conversions for enc1 / dec3 operands
    split_bf16<<<dim3(IMG / 256, BATCH), blk>>>(x, xh, xl, BATCH, IMG, IMG);
    split_bf16<<<dim3((W1N_PAD + 255) / 256, IMG), blk>>>(enc_w1, w1h, w1l, IMG, H1, W1N_PAD);
    split_bf16<<<dim3(IMG / 256, W3K_PAD), blk>>>(dec_w3, w3h, w3l, H2, IMG, IMG);

    // ---- encoder
    mma_gemm_split<ACT_ELU><<<dim3(W1N_PAD / BN, BATCH / BM), blk, SMEM_BYTES>>>(
        xh, xl, IMG, w1h, w1l, W1N_PAD, enc_b1, h1, H1, H1, IMG / BK);
    gemm_bias_act<ACT_ELU><<<dim3((H2 + SBN - 1) / SBN, BATCH / SBM), blk>>>(
        h1, enc_w2, enc_b2, h2, BATCH, H2, H1);
    gemm_bias_act<ACT_NONE><<<dim3((D + SBN - 1) / SBN, BATCH / SBM), blk>>>(
        h2, logvar_w, logvar_b, lv_o, BATCH, D, H2);

    // ---- latent
    bmat_kernel<<<1, 256>>>(W, bm_o);
    z_kernel<<<BATCH / 256, 256>>>(W, lv_o, noise, z_o, bz_o);

    // ---- decoder
    gemm_bias_act<ACT_ELU><<<dim3((H2 + SBN - 1) / SBN, BATCH / SBM), blk>>>(
        z_o, dec_w1, dec_b1, g1, BATCH, H2, D);
    gemm_bias_act<ACT_ELU><<<dim3((H2 + SBN - 1) / SBN, BATCH / SBM), blk>>>(
        g1, dec_w2, dec_b2, g2, BATCH, H2, H2);
    split_bf16<<<dim3((W3K_PAD + 255) / 256, BATCH), blk>>>(g2, g2h, g2l, BATCH, H2, W3K_PAD);
    mma_gemm_split<ACT_TANH><<<dim3(IMG / BN, BATCH / BM), blk, SMEM_BYTES>>>(
        g2h, g2l, W3K_PAD, w3h, w3l, IMG, dec_b3, xh_o, IMG, IMG, W3K_PAD / BK);
}

// round 3
// speedup vs baseline: 2.5208x; 1.1207x over previous
#include <cuda_runtime.h>
#include <cuda_bf16.h>
#include <math.h>
#include <stdint.h>

// ---------------------------------------------------------------------------
// VAE forward. Round 3: bf16 hi/lo 4-product split (fp32-class accuracy),
// 3-stage cp.async pipeline, split-K for enc1 (grid 120 -> 240 CTAs).
// ---------------------------------------------------------------------------

#define BATCH 1024
#define IMG   27648
#define H1    900
#define H2    300
#define D     16

enum { ACT_NONE = 0, ACT_ELU = 1, ACT_TANH = 2, ACT_RAW = 3 };

// ---------------- scratch (__device__ globals; no allocs allowed) ----------
__device__ float g_h1[BATCH * H1];
__device__ float g_h2[BATCH * H2];
__device__ float g_g1[BATCH * H2];
__device__ float g_g2[BATCH * H2];

#define W1N_PAD 960          // 900 -> 15*64
#define W3K_PAD 320          // 300 -> 10*32
#define KSLICES 2
#define KSLICE  (IMG / KSLICES)   // 13824

__device__ float g_ws[KSLICES * BATCH * W1N_PAD];   // split-K partials (fp32)

__device__ __nv_bfloat16 g_xh[BATCH * IMG];
__device__ __nv_bfloat16 g_xl[BATCH * IMG];
__device__ __nv_bfloat16 g_w1h[IMG * W1N_PAD];
__device__ __nv_bfloat16 g_w1l[IMG * W1N_PAD];
__device__ __nv_bfloat16 g_w3h[W3K_PAD * IMG];
__device__ __nv_bfloat16 g_w3l[W3K_PAD * IMG];
__device__ __nv_bfloat16 g_g2h[BATCH * W3K_PAD];
__device__ __nv_bfloat16 g_g2l[BATCH * W3K_PAD];

// ---------------- fp32 -> (hi, lo) bf16 split, 4 elems/thread --------------
__global__ void split_bf16_v4(const float* __restrict__ src,
                              __nv_bfloat16* __restrict__ hi,
                              __nv_bfloat16* __restrict__ lo,
                              int src_rows, int src_cols, int dst_cols)
{
    int c = (blockIdx.x * 256 + threadIdx.x) * 4;
    int r = blockIdx.y;
    if (c >= dst_cols) return;
    float v[4];
    if (r < src_rows && c + 3 < src_cols) {
        float4 f = *(const float4*)&src[(size_t)r * src_cols + c];
        v[0] = f.x; v[1] = f.y; v[2] = f.z; v[3] = f.w;
    } else {
#pragma unroll
        for (int i = 0; i < 4; i++)
            v[i] = (r < src_rows && c + i < src_cols)
                 ? src[(size_t)r * src_cols + c + i] : 0.f;
    }
    __nv_bfloat16 h4[4], l4[4];
#pragma unroll
    for (int i = 0; i < 4; i++) {
        h4[i] = __float2bfloat16_rn(v[i]);
        l4[i] = __float2bfloat16_rn(v[i] - __bfloat162float(h4[i]));
    }
    size_t o = (size_t)r * dst_cols + c;
    *(uint64_t*)&hi[o] = *(uint64_t*)h4;
    *(uint64_t*)&lo[o] = *(uint64_t*)l4;
}

// ---------------- tensor-core GEMM (bf16x4 split, 3-stage pipeline) --------
#define BM 128
#define BN 64
#define BK 32
#define ASTR 40
#define BSTR 72
#define STAGES 3

#define A_BYTES (BM * ASTR * 2)                     // 10240
#define B_BYTES (BK * BSTR * 2)                     // 4608
#define STAGE_BYTES (2 * A_BYTES + 2 * B_BYTES)     // 29696
#define SMEM_BYTES (STAGES * STAGE_BYTES)           // 89088

__device__ __forceinline__ void cp16(void* s, const void* g)
{
    uint32_t sa = (uint32_t)__cvta_generic_to_shared(s);
    asm volatile("cp.async.cg.shared.global [%0], [%1], 16;\n" :: "r"(sa), "l"(g));
}

__device__ __forceinline__ void ldsm_x4(uint32_t* r, const void* p)
{
    uint32_t a = (uint32_t)__cvta_generic_to_shared(p);
    asm volatile("ldmatrix.sync.aligned.m8n8.x4.shared.b16 {%0,%1,%2,%3}, [%4];\n"
                 : "=r"(r[0]), "=r"(r[1]), "=r"(r[2]), "=r"(r[3]) : "r"(a));
}

__device__ __forceinline__ void ldsm_x4_t(uint32_t* r, const void* p)
{
    uint32_t a = (uint32_t)__cvta_generic_to_shared(p);
    asm volatile("ldmatrix.sync.aligned.m8n8.x4.trans.shared.b16 {%0,%1,%2,%3}, [%4];\n"
                 : "=r"(r[0]), "=r"(r[1]), "=r"(r[2]), "=r"(r[3]) : "r"(a));
}

__device__ __forceinline__ void mma16816(float* c, const uint32_t* a, const uint32_t* b)
{
    asm volatile(
        "mma.sync.aligned.m16n8k16.row.col.f32.bf16.bf16.f32 "
        "{%0,%1,%2,%3}, {%4,%5,%6,%7}, {%8,%9}, {%0,%1,%2,%3};\n"
        : "+f"(c[0]), "+f"(c[1]), "+f"(c[2]), "+f"(c[3])
        : "r"(a[0]), "r"(a[1]), "r"(a[2]), "r"(a[3]), "r"(b[0]), "r"(b[1]));
}

// C[M,N] = act(Ah@Bh + Ah@Bl + Al@Bh + Al@Bl + bias)
// blockIdx.z selects a K slice (split-K); ACT_RAW stores raw partials.
template <int ACT>
__global__ void __launch_bounds__(256, 2)
mma_gemm_split(const __nv_bfloat16* __restrict__ Ah, const __nv_bfloat16* __restrict__ Al,
               int lda,
               const __nv_bfloat16* __restrict__ Bh, const __nv_bfloat16* __restrict__ Bl,
               int ldb,
               const float* __restrict__ bias, float* __restrict__ C, int ldc,
               int N, int KT, int kslice_kt)
{
    extern __shared__ char smem[];
    __nv_bfloat16 *sAh[STAGES], *sAl[STAGES], *sBh[STAGES], *sBl[STAGES];
#pragma unroll
    for (int s = 0; s < STAGES; s++) {
        char* base = smem + s * STAGE_BYTES;
        sAh[s] = (__nv_bfloat16*)(base);
        sAl[s] = (__nv_bfloat16*)(base + A_BYTES);
        sBh[s] = (__nv_bfloat16*)(base + 2 * A_BYTES);
        sBl[s] = (__nv_bfloat16*)(base + 2 * A_BYTES + B_BYTES);
    }

    const int t    = threadIdx.x;
    const int lane = t & 31;
    const int wid  = t >> 5;
    const int wm   = wid & 3;
    const int wn   = wid >> 2;
    const int m0   = blockIdx.y * BM;
    const int n0   = blockIdx.x * BN;
    const int kofs = blockIdx.z * kslice_kt * BK;

    float acc[2][4][4];
#pragma unroll
    for (int i = 0; i < 2; i++)
#pragma unroll
        for (int j = 0; j < 4; j++)
#pragma unroll
            for (int q = 0; q < 4; q++) acc[i][j][q] = 0.f;

    auto load_stage = [&](int s, int kt) {
        const int k0 = kofs + kt * BK;
#pragma unroll
        for (int i = 0; i < 2; i++) {
            int c   = t + i * 256;
            int row = c >> 2;
            int seg = (c & 3) << 3;
            size_t go = (size_t)(m0 + row) * lda + k0 + seg;
            int    so = row * ASTR + seg;
            cp16(&sAh[s][so], &Ah[go]);
            cp16(&sAl[s][so], &Al[go]);
        }
        {
            int row = t >> 3;
            int seg = (t & 7) << 3;
            size_t go = (size_t)(k0 + row) * ldb + n0 + seg;
            int    so = row * BSTR + seg;
            cp16(&sBh[s][so], &Bh[go]);
            cp16(&sBl[s][so], &Bl[go]);
        }
        asm volatile("cp.async.commit_group;\n");
    };

    load_stage(0, 0);
    if (KT > 1) load_stage(1, 1);

    int slot = 0;
    for (int kt = 0; kt < KT; kt++) {
        if (kt < KT - 1) asm volatile("cp.async.wait_group 1;\n");
        else             asm volatile("cp.async.wait_group 0;\n");
        __syncthreads();
        if (kt + 2 < KT) {
            int ns = slot + 2; if (ns >= STAGES) ns -= STAGES;
            load_stage(ns, kt + 2);
        }

#pragma unroll
        for (int ks = 0; ks < 2; ks++) {
            uint32_t afh[2][4], afl[2][4];
#pragma unroll
            for (int mt = 0; mt < 2; mt++) {
                int r = wm * 32 + mt * 16 + (lane & 15);
                int c = ks * 16 + ((lane >> 4) << 3);
                ldsm_x4(afh[mt], &sAh[slot][r * ASTR + c]);
                ldsm_x4(afl[mt], &sAl[slot][r * ASTR + c]);
            }
            uint32_t bfh[4][2], bfl[4][2];
#pragma unroll
            for (int np = 0; np < 2; np++) {
                int r = ks * 16 + (lane & 15);
                int c = wn * 32 + np * 16 + ((lane >> 4) << 3);
                uint32_t rh[4], rl[4];
                ldsm_x4_t(rh, &sBh[slot][r * BSTR + c]);
                ldsm_x4_t(rl, &sBl[slot][r * BSTR + c]);
                bfh[np * 2][0] = rh[0]; bfh[np * 2][1] = rh[1];
                bfh[np * 2 + 1][0] = rh[2]; bfh[np * 2 + 1][1] = rh[3];
                bfl[np * 2][0] = rl[0]; bfl[np * 2][1] = rl[1];
                bfl[np * 2 + 1][0] = rl[2]; bfl[np * 2 + 1][1] = rl[3];
            }
#pragma unroll
            for (int mt = 0; mt < 2; mt++)
#pragma unroll
                for (int nt = 0; nt < 4; nt++) {
                    mma16816(acc[mt][nt], afh[mt], bfh[nt]);
                    mma16816(acc[mt][nt], afh[mt], bfl[nt]);
                    mma16816(acc[mt][nt], afl[mt], bfh[nt]);
                    mma16816(acc[mt][nt], afl[mt], bfl[nt]);
                }
        }
        slot++; if (slot >= STAGES) slot -= STAGES;
    }

    // epilogue
    float* Cz = C + (size_t)blockIdx.z * ((size_t)BATCH * ldc);
#pragma unroll
    for (int mt = 0; mt < 2; mt++) {
#pragma unroll
        for (int nt = 0; nt < 4; nt++) {
            int col = n0 + wn * 32 + nt * 8 + (lane & 3) * 2;
            if (col >= N) continue;
            float b0 = 0.f, b1 = 0.f;
            if (ACT != ACT_RAW) {
                b0 = bias[col];
                b1 = (col + 1 < N) ? bias[col + 1] : 0.f;
            }
#pragma unroll
            for (int h = 0; h < 2; h++) {
                int row = m0 + wm * 32 + mt * 16 + (lane >> 2) + h * 8;
                float v0 = acc[mt][nt][2 * h + 0] + b0;
                float v1 = acc[mt][nt][2 * h + 1] + b1;
                if (ACT == ACT_ELU)  { v0 = v0 > 0.f ? v0 : expm1f(v0);
                                       v1 = v1 > 0.f ? v1 : expm1f(v1); }
                if (ACT == ACT_TANH) { v0 = tanhf(v0); v1 = tanhf(v1); }
                if (col + 1 < N) {
                    *(float2*)&Cz[(size_t)row * ldc + col] = make_float2(v0, v1);
                } else {
                    Cz[(size_t)row * ldc + col] = v0;
                }
            }
        }
    }
}

// split-K combine: h1 = elu(ws0 + ws1 + bias)
__global__ void reduce_elu(const float* __restrict__ ws,
                           const float* __restrict__ bias,
                           float* __restrict__ outp)
{
    int i = blockIdx.x * 256 + threadIdx.x;     // over 1024*900
    if (i >= BATCH * H1) return;
    int m = i / H1, n = i - m * H1;
    float v = ws[(size_t)m * W1N_PAD + n]
            + ws[(size_t)BATCH * W1N_PAD + (size_t)m * W1N_PAD + n]
            + bias[n];
    outp[i] = v > 0.f ? v : expm1f(v);
}

// ---------------- fp32 SIMT GEMM for the small layers ----------------------
#define SBM 64
#define SBN 64
#define SBK 16

template <int ACT>
__global__ void __launch_bounds__(256)
gemm_bias_act(const float* __restrict__ A, const float* __restrict__ B,
              const float* __restrict__ bias, float* __restrict__ C,
              int M, int N, int K)
{
    __shared__ float As[SBK][SBM + 1];
    __shared__ float Bs[SBK][SBN];

    const int t  = threadIdx.x;
    const int tx = t & 15;
    const int ty = t >> 4;
    const int n0 = blockIdx.x * SBN;
    const int m0 = blockIdx.y * SBM;

    float acc[4][4];
#pragma unroll
    for (int i = 0; i < 4; i++)
#pragma unroll
        for (int j = 0; j < 4; j++) acc[i][j] = 0.f;

    for (int k0 = 0; k0 < K; k0 += SBK) {
#pragma unroll
        for (int i = 0; i < 4; i++) {
            int e = t + i * 256;
            int c = e & 15, r = e >> 4;
            int gm = m0 + r, gk = k0 + c;
            As[c][r] = (gm < M && gk < K) ? A[(size_t)gm * K + gk] : 0.f;
        }
#pragma unroll
        for (int i = 0; i < 4; i++) {
            int e = t + i * 256;
            int n = e & 63, kk = e >> 6;
            int gk = k0 + kk, gn = n0 + n;
            Bs[kk][n] = (gk < K && gn < N) ? B[(size_t)gk * N + gn] : 0.f;
        }
        __syncthreads();
#pragma unroll
        for (int k = 0; k < SBK; k++) {
            float a[4], b[4];
#pragma unroll
            for (int i = 0; i < 4; i++) a[i] = As[k][ty * 4 + i];
#pragma unroll
            for (int j = 0; j < 4; j++) b[j] = Bs[k][tx * 4 + j];
#pragma unroll
            for (int i = 0; i < 4; i++)
#pragma unroll
                for (int j = 0; j < 4; j++)
                    acc[i][j] = fmaf(a[i], b[j], acc[i][j]);
        }
        __syncthreads();
    }

#pragma unroll
    for (int i = 0; i < 4; i++) {
        int gm = m0 + ty * 4 + i;
        if (gm >= M) continue;
#pragma unroll
        for (int j = 0; j < 4; j++) {
            int gn = n0 + tx * 4 + j;
            if (gn >= N) continue;
            float v = acc[i][j] + bias[gn];
            if (ACT == ACT_ELU)  v = (v > 0.f) ? v : expm1f(v);
            if (ACT == ACT_TANH) v = tanhf(v);
            C[(size_t)gm * N + gn] = v;
        }
    }
}

// ---------------- latent path ----------------------------------------------
__global__ void bmat_kernel(const float* __restrict__ W, float* __restrict__ bmat)
{
    int t = threadIdx.x;
    int i = t >> 4, j = t & 15;
    bmat[t] = (j > i) ? W[t] * (float)(j - i) : 0.f;
}

__global__ void z_kernel(const float* __restrict__ W,
                         const float* __restrict__ logvar,
                         const float* __restrict__ noise,
                         float* __restrict__ z_out,
                         float* __restrict__ bz_out)
{
    __shared__ float sB[D][D];
    int t = threadIdx.x;
    {
        int i = t >> 4, j = t & 15;
        sB[i][j] = (j > i) ? W[t] * (float)(j - i) : 0.f;
    }
    __syncthreads();

    int b = blockIdx.x * 256 + t;
    float eps[D], zz[D], bz[D];
#pragma unroll
    for (int j = 0; j < D; j++)
        eps[j] = expf(0.5f * logvar[b * D + j]) * noise[b * D + j];
#pragma unroll
    for (int j = 0; j < D; j++) {
        float sum = 0.f;
#pragma unroll
        for (int i = 0; i < D; i++)
            if (i < j) sum = fmaf(zz[i], sB[i][j], sum);
        bz[j] = sum;
        zz[j] = eps[j] + sum;
    }
#pragma unroll
    for (int j = 0; j < D; j++) {
        z_out[b * D + j]  = zz[j];
        bz_out[b * D + j] = bz[j];
    }
}

// ---------------- launch -----------------------------------------------------
extern "C" void kernel_launch(void* const* d_in, const int* in_sizes, int n_in,
                              void* d_out, int out_size)
{
    (void)in_sizes; (void)n_in; (void)out_size;

    const float* x        = (const float*)d_in[0];
    const float* noise    = (const float*)d_in[1];
    const float* enc_w1   = (const float*)d_in[2];
    const float* enc_b1   = (const float*)d_in[3];
    const float* enc_w2   = (const float*)d_in[4];
    const float* enc_b2   = (const float*)d_in[5];
    const float* logvar_w = (const float*)d_in[6];
    const float* logvar_b = (const float*)d_in[7];
    const float* W        = (const float*)d_in[8];
    const float* dec_w1   = (const float*)d_in[9];
    const float* dec_b1   = (const float*)d_in[10];
    const float* dec_w2   = (const float*)d_in[11];
    const float* dec_b2   = (const float*)d_in[12];
    const float* dec_w3   = (const float*)d_in[13];
    const float* dec_b3   = (const float*)d_in[14];

    float* out  = (float*)d_out;
    float* z_o  = out;
    float* lv_o = out + BATCH * D;
    float* bz_o = out + 2 * BATCH * D;
    float* bm_o = out + 3 * BATCH * D;
    float* xh_o = out + 3 * BATCH * D + D * D;

    float *h1, *h2, *g1, *g2, *ws;
    cudaGetSymbolAddress((void**)&h1, g_h1);
    cudaGetSymbolAddress((void**)&h2, g_h2);
    cudaGetSymbolAddress((void**)&g1, g_g1);
    cudaGetSymbolAddress((void**)&g2, g_g2);
    cudaGetSymbolAddress((void**)&ws, g_ws);
    __nv_bfloat16 *xh, *xl, *w1h, *w1l, *w3h, *w3l, *g2h, *g2l;
    cudaGetSymbolAddress((void**)&xh,  g_xh);
    cudaGetSymbolAddress((void**)&xl,  g_xl);
    cudaGetSymbolAddress((void**)&w1h, g_w1h);
    cudaGetSymbolAddress((void**)&w1l, g_w1l);
    cudaGetSymbolAddress((void**)&w3h, g_w3h);
    cudaGetSymbolAddress((void**)&w3l, g_w3l);
    cudaGetSymbolAddress((void**)&g2h, g_g2h);
    cudaGetSymbolAddress((void**)&g2l, g_g2l);

    cudaFuncSetAttribute(mma_gemm_split<ACT_RAW>,
                         cudaFuncAttributeMaxDynamicSharedMemorySize, SMEM_BYTES);
    cudaFuncSetAttribute(mma_gemm_split<ACT_TANH>,
                         cudaFuncAttributeMaxDynamicSharedMemorySize, SMEM_BYTES);

    dim3 blk(256);

    // ---- bf16 splits
    split_bf16_v4<<<dim3(IMG / 1024, BATCH), blk>>>(x, xh, xl, BATCH, IMG, IMG);
    split_bf16_v4<<<dim3(1, IMG), blk>>>(enc_w1, w1h, w1l, IMG, H1, W1N_PAD);
    split_bf16_v4<<<dim3(IMG / 1024, W3K_PAD), blk>>>(dec_w3, w3h, w3l, H2, IMG, IMG);

    // ---- encoder: enc1 via split-K tensor GEMM + combine
    mma_gemm_split<ACT_RAW><<<dim3(W1N_PAD / BN, BATCH / BM, KSLICES), blk, SMEM_BYTES>>>(
        xh, xl, IMG, w1h, w1l, W1N_PAD, nullptr, ws, W1N_PAD, W1N_PAD,
        KSLICE / BK, KSLICE / BK);
    reduce_elu<<<(BATCH * H1 + 255) / 256, blk>>>(ws, enc_b1, h1);

    gemm_bias_act<ACT_ELU><<<dim3((H2 + SBN - 1) / SBN, BATCH / SBM), blk>>>(
        h1, enc_w2, enc_b2, h2, BATCH, H2, H1);
    gemm_bias_act<ACT_NONE><<<dim3((D + SBN - 1) / SBN, BATCH / SBM), blk>>>(
        h2, logvar_w, logvar_b, lv_o, BATCH, D, H2);

    // ---- latent
    bmat_kernel<<<1, 256>>>(W, bm_o);
    z_kernel<<<BATCH / 256, 256>>>(W, lv_o, noise, z_o, bz_o);

    // ---- decoder
    gemm_bias_act<ACT_ELU><<<dim3((H2 + SBN - 1) / SBN, BATCH / SBM), blk>>>(
        z_o, dec_w1, dec_b1, g1, BATCH, H2, D);
    gemm_bias_act<ACT_ELU><<<dim3((H2 + SBN - 1) / SBN, BATCH / SBM), blk>>>(
        g1, dec_w2, dec_b2, g2, BATCH, H2, H2);
    split_bf16_v4<<<dim3(1, BATCH), blk>>>(g2, g2h, g2l, BATCH, H2, W3K_PAD);
    mma_gemm_split<ACT_TANH><<<dim3(IMG / BN, BATCH / BM, 1), blk, SMEM_BYTES>>>(
        g2h, g2l, W3K_PAD, w3h, w3l, IMG, dec_b3, xh_o, IMG, IMG,
        W3K_PAD / BK, W3K_PAD / BK);
}

// round 6
// speedup vs baseline: 2.9547x; 1.1721x over previous
#include <cuda_runtime.h>
#include <cuda_bf16.h>
#include <math.h>
#include <stdint.h>

// ---------------------------------------------------------------------------
// VAE forward. Round 6: R5 design with alignment fix (ASTR 36 -> 40 so all
// cp.async/ldmatrix addresses are 16B-aligned). mma.sync bf16x4, 64x64 warp
// tiles, CTA 128x128, 3-stage cp.async, enc1 split-K=4, enc2/dec2 on tensor
// path, fused logvar+triangular-solve.
// ---------------------------------------------------------------------------

#define BATCH 1024
#define IMG   27648
#define H1    900
#define H2    300
#define D     16

#define W1N 1024           // enc1 N padded (900 -> 1024)
#define H1K 960            // enc2 K padded (900 -> 960)
#define H2N 384            // enc2/dec2 N padded (300 -> 384)
#define H2K 320            // dec2/dec3 K padded (300 -> 320)
#define KSLICES 4

enum { ACT_NONE = 0, ACT_ELU = 1, ACT_TANH = 2, ACT_RAW = 3 };

// ---------------- scratch (__device__ globals; no allocs allowed) ----------
__device__ float g_h1[BATCH * H1];
__device__ float g_h2[BATCH * H2];
__device__ float g_g1[BATCH * H2];
__device__ float g_g2[BATCH * H2];
__device__ float g_ws[KSLICES * BATCH * W1N];

__device__ __align__(16) __nv_bfloat16 g_xh[(size_t)BATCH * IMG];
__device__ __align__(16) __nv_bfloat16 g_xl[(size_t)BATCH * IMG];
__device__ __align__(16) __nv_bfloat16 g_w1h[(size_t)IMG * W1N];
__device__ __align__(16) __nv_bfloat16 g_w1l[(size_t)IMG * W1N];
__device__ __align__(16) __nv_bfloat16 g_h1h[(size_t)BATCH * H1K];
__device__ __align__(16) __nv_bfloat16 g_h1l[(size_t)BATCH * H1K];
__device__ __align__(16) __nv_bfloat16 g_w2h[(size_t)H1K * H2N];
__device__ __align__(16) __nv_bfloat16 g_w2l[(size_t)H1K * H2N];
__device__ __align__(16) __nv_bfloat16 g_g1h[(size_t)BATCH * H2K];
__device__ __align__(16) __nv_bfloat16 g_g1l[(size_t)BATCH * H2K];
__device__ __align__(16) __nv_bfloat16 g_dw2h[(size_t)H2K * H2N];
__device__ __align__(16) __nv_bfloat16 g_dw2l[(size_t)H2K * H2N];
__device__ __align__(16) __nv_bfloat16 g_g2h[(size_t)BATCH * H2K];
__device__ __align__(16) __nv_bfloat16 g_g2l[(size_t)BATCH * H2K];
__device__ __align__(16) __nv_bfloat16 g_w3h[(size_t)H2K * IMG];
__device__ __align__(16) __nv_bfloat16 g_w3l[(size_t)H2K * IMG];

// ---------------- fp32 -> (hi, lo) bf16 split with 2D zero padding ---------
__global__ void split_bf16_v4(const float* __restrict__ src,
                              __nv_bfloat16* __restrict__ hi,
                              __nv_bfloat16* __restrict__ lo,
                              int src_rows, int src_cols, int dst_cols)
{
    int c = (blockIdx.x * 256 + threadIdx.x) * 4;
    int r = blockIdx.y;
    if (c >= dst_cols) return;
    float v[4];
    if (r < src_rows && c + 3 < src_cols) {
        float4 f = *(const float4*)&src[(size_t)r * src_cols + c];
        v[0] = f.x; v[1] = f.y; v[2] = f.z; v[3] = f.w;
    } else {
#pragma unroll
        for (int i = 0; i < 4; i++)
            v[i] = (r < src_rows && c + i < src_cols)
                 ? src[(size_t)r * src_cols + c + i] : 0.f;
    }
    __nv_bfloat16 h4[4], l4[4];
#pragma unroll
    for (int i = 0; i < 4; i++) {
        h4[i] = __float2bfloat16_rn(v[i]);
        l4[i] = __float2bfloat16_rn(v[i] - __bfloat162float(h4[i]));
    }
    size_t o = (size_t)r * dst_cols + c;
    *(uint64_t*)&hi[o] = *(uint64_t*)h4;
    *(uint64_t*)&lo[o] = *(uint64_t*)l4;
}

// ---------------- tensor-core GEMM (bf16x4, 64x64 warp tiles) --------------
#define TBM 128
#define TBN 128
#define TBK 32
#define ASTR 40            // bf16 stride for A rows (80B, 16B-multiple)
#define BSTR 136           // bf16 stride for B rows (272B, 16B-multiple)
#define NSTG 3

#define A_BYTES (TBM * ASTR * 2)                 // 10240
#define B_BYTES (TBK * BSTR * 2)                 // 8704
#define STAGE_BYTES (2 * A_BYTES + 2 * B_BYTES)  // 37888
#define SMEM_BYTES (NSTG * STAGE_BYTES)          // 113664

__device__ __forceinline__ void cp16(void* s, const void* g)
{
    uint32_t sa = (uint32_t)__cvta_generic_to_shared(s);
    asm volatile("cp.async.cg.shared.global [%0], [%1], 16;\n" :: "r"(sa), "l"(g));
}

__device__ __forceinline__ void ldsm_x4(uint32_t* r, const void* p)
{
    uint32_t a = (uint32_t)__cvta_generic_to_shared(p);
    asm volatile("ldmatrix.sync.aligned.m8n8.x4.shared.b16 {%0,%1,%2,%3}, [%4];\n"
                 : "=r"(r[0]), "=r"(r[1]), "=r"(r[2]), "=r"(r[3]) : "r"(a));
}

__device__ __forceinline__ void ldsm_x4_t(uint32_t* r, const void* p)
{
    uint32_t a = (uint32_t)__cvta_generic_to_shared(p);
    asm volatile("ldmatrix.sync.aligned.m8n8.x4.trans.shared.b16 {%0,%1,%2,%3}, [%4];\n"
                 : "=r"(r[0]), "=r"(r[1]), "=r"(r[2]), "=r"(r[3]) : "r"(a));
}

__device__ __forceinline__ void mma16816(float* c, const uint32_t* a, const uint32_t* b)
{
    asm volatile(
        "mma.sync.aligned.m16n8k16.row.col.f32.bf16.bf16.f32 "
        "{%0,%1,%2,%3}, {%4,%5,%6,%7}, {%8,%9}, {%0,%1,%2,%3};\n"
        : "+f"(c[0]), "+f"(c[1]), "+f"(c[2]), "+f"(c[3])
        : "r"(a[0]), "r"(a[1]), "r"(a[2]), "r"(a[3]), "r"(b[0]), "r"(b[1]));
}

// C[M,N] = act(Ah@Bh + Ah@Bl + Al@Bh + Al@Bl + bias); A [M,K], B [K,N].
// blockIdx.z = K-slice (ACT_RAW stores raw partials at slice offset).
template <int ACT>
__global__ void __launch_bounds__(128, 2)
mma_gemm_big(const __nv_bfloat16* __restrict__ Ah, const __nv_bfloat16* __restrict__ Al,
             int lda,
             const __nv_bfloat16* __restrict__ Bh, const __nv_bfloat16* __restrict__ Bl,
             int ldb,
             const float* __restrict__ bias, float* __restrict__ C, int ldc,
             int Nreal, int KT, int kslice_kt)
{
    extern __shared__ char smem[];
    __nv_bfloat16 *sAh[NSTG], *sAl[NSTG], *sBh[NSTG], *sBl[NSTG];
#pragma unroll
    for (int s = 0; s < NSTG; s++) {
        char* base = smem + s * STAGE_BYTES;
        sAh[s] = (__nv_bfloat16*)(base);
        sAl[s] = (__nv_bfloat16*)(base + A_BYTES);
        sBh[s] = (__nv_bfloat16*)(base + 2 * A_BYTES);
        sBl[s] = (__nv_bfloat16*)(base + 2 * A_BYTES + B_BYTES);
    }

    const int t    = threadIdx.x;
    const int lane = t & 31;
    const int wid  = t >> 5;
    const int wm   = wid & 1;        // 2 warp rows (64 each)
    const int wn   = wid >> 1;       // 2 warp cols (64 each)
    const int m0   = blockIdx.y * TBM;
    const int n0   = blockIdx.x * TBN;
    const int kofs = blockIdx.z * kslice_kt * TBK;

    float acc[4][8][4];
#pragma unroll
    for (int i = 0; i < 4; i++)
#pragma unroll
        for (int j = 0; j < 8; j++)
#pragma unroll
            for (int q = 0; q < 4; q++) acc[i][j][q] = 0.f;

    auto load_stage = [&](int s, int kt) {
        const int k0 = kofs + kt * TBK;
#pragma unroll
        for (int i = 0; i < 4; i++) {            // A: 512 idx (row, 16B seg)
            int idx = t + i * 128;
            int row = idx >> 2, seg = idx & 3;
            int so = row * ASTR + seg * 8;
            size_t go = (size_t)(m0 + row) * lda + k0 + seg * 8;
            cp16(&sAh[s][so], &Ah[go]);
            cp16(&sAl[s][so], &Al[go]);
        }
#pragma unroll
        for (int i = 0; i < 4; i++) {            // B: 512 idx
            int idx = t + i * 128;
            int row = idx >> 4, seg = idx & 15;
            int so = row * BSTR + seg * 8;
            size_t go = (size_t)(k0 + row) * ldb + n0 + seg * 8;
            cp16(&sBh[s][so], &Bh[go]);
            cp16(&sBl[s][so], &Bl[go]);
        }
        asm volatile("cp.async.commit_group;\n");
    };

    load_stage(0, 0);
    if (KT > 1) load_stage(1, 1);

    int slot = 0;
    for (int kt = 0; kt < KT; kt++) {
        if (kt < KT - 1) asm volatile("cp.async.wait_group 1;\n" ::: "memory");
        else             asm volatile("cp.async.wait_group 0;\n" ::: "memory");
        __syncthreads();
        if (kt + 2 < KT) {
            int ns = slot + 2; if (ns >= NSTG) ns -= NSTG;
            load_stage(ns, kt + 2);
        }

#pragma unroll
        for (int ks = 0; ks < 2; ks++) {
            uint32_t afh[4][4], afl[4][4];
#pragma unroll
            for (int mt = 0; mt < 4; mt++) {
                int r = wm * 64 + mt * 16 + (lane & 15);
                int c = ks * 16 + ((lane >> 4) << 3);
                ldsm_x4(afh[mt], &sAh[slot][r * ASTR + c]);
                ldsm_x4(afl[mt], &sAl[slot][r * ASTR + c]);
            }
            uint32_t bfh[8][2], bfl[8][2];
#pragma unroll
            for (int np = 0; np < 4; np++) {
                int r = ks * 16 + (lane & 15);
                int c = wn * 64 + np * 16 + ((lane >> 4) << 3);
                uint32_t rh[4], rl[4];
                ldsm_x4_t(rh, &sBh[slot][r * BSTR + c]);
                ldsm_x4_t(rl, &sBl[slot][r * BSTR + c]);
                bfh[np * 2][0] = rh[0]; bfh[np * 2][1] = rh[1];
                bfh[np * 2 + 1][0] = rh[2]; bfh[np * 2 + 1][1] = rh[3];
                bfl[np * 2][0] = rl[0]; bfl[np * 2][1] = rl[1];
                bfl[np * 2 + 1][0] = rl[2]; bfl[np * 2 + 1][1] = rl[3];
            }
#pragma unroll
            for (int mt = 0; mt < 4; mt++)
#pragma unroll
                for (int nt = 0; nt < 8; nt++) {
                    mma16816(acc[mt][nt], afh[mt], bfh[nt]);
                    mma16816(acc[mt][nt], afh[mt], bfl[nt]);
                    mma16816(acc[mt][nt], afl[mt], bfh[nt]);
                    mma16816(acc[mt][nt], afl[mt], bfl[nt]);
                }
        }
        slot++; if (slot >= NSTG) slot -= NSTG;
    }

    float* Cz = C + (size_t)blockIdx.z * ((size_t)BATCH * ldc);
#pragma unroll
    for (int mt = 0; mt < 4; mt++) {
#pragma unroll
        for (int nt = 0; nt < 8; nt++) {
            int col = n0 + wn * 64 + nt * 8 + (lane & 3) * 2;
            if (col >= Nreal) continue;
            float b0 = 0.f, b1 = 0.f;
            if (ACT != ACT_RAW) { b0 = bias[col]; b1 = bias[col + 1]; }
#pragma unroll
            for (int h = 0; h < 2; h++) {
                int row = m0 + wm * 64 + mt * 16 + (lane >> 2) + h * 8;
                float v0 = acc[mt][nt][2 * h + 0] + b0;
                float v1 = acc[mt][nt][2 * h + 1] + b1;
                if (ACT == ACT_ELU)  { v0 = v0 > 0.f ? v0 : expm1f(v0);
                                       v1 = v1 > 0.f ? v1 : expm1f(v1); }
                if (ACT == ACT_TANH) { v0 = tanhf(v0); v1 = tanhf(v1); }
                *(float2*)&Cz[(size_t)row * ldc + col] = make_float2(v0, v1);
            }
        }
    }
}

// split-K combine: h1 = elu(sum_z ws[z] + bias)
__global__ void reduce_elu(const float* __restrict__ ws,
                           const float* __restrict__ bias,
                           float* __restrict__ outp)
{
    int i = blockIdx.x * 256 + threadIdx.x;
    if (i >= BATCH * H1) return;
    int m = i / H1, n = i - m * H1;
    size_t o = (size_t)m * W1N + n;
    float v = bias[n];
#pragma unroll
    for (int z = 0; z < KSLICES; z++)
        v += ws[(size_t)z * BATCH * W1N + o];
    outp[i] = v > 0.f ? v : expm1f(v);
}

// ---------------- fp32 SIMT GEMM (dec1 only, K=16) --------------------------
#define SBM 64
#define SBN 64
#define SBK 16

template <int ACT>
__global__ void __launch_bounds__(256)
gemm_bias_act(const float* __restrict__ A, const float* __restrict__ B,
              const float* __restrict__ bias, float* __restrict__ C,
              int M, int N, int K)
{
    __shared__ float As[SBK][SBM + 1];
    __shared__ float Bs[SBK][SBN];

    const int t  = threadIdx.x;
    const int tx = t & 15;
    const int ty = t >> 4;
    const int n0 = blockIdx.x * SBN;
    const int m0 = blockIdx.y * SBM;

    float acc[4][4];
#pragma unroll
    for (int i = 0; i < 4; i++)
#pragma unroll
        for (int j = 0; j < 4; j++) acc[i][j] = 0.f;

    for (int k0 = 0; k0 < K; k0 += SBK) {
#pragma unroll
        for (int i = 0; i < 4; i++) {
            int e = t + i * 256;
            int c = e & 15, r = e >> 4;
            int gm = m0 + r, gk = k0 + c;
            As[c][r] = (gm < M && gk < K) ? A[(size_t)gm * K + gk] : 0.f;
        }
#pragma unroll
        for (int i = 0; i < 4; i++) {
            int e = t + i * 256;
            int n = e & 63, kk = e >> 6;
            int gk = k0 + kk, gn = n0 + n;
            Bs[kk][n] = (gk < K && gn < N) ? B[(size_t)gk * N + gn] : 0.f;
        }
        __syncthreads();
#pragma unroll
        for (int k = 0; k < SBK; k++) {
            float a[4], b[4];
#pragma unroll
            for (int i = 0; i < 4; i++) a[i] = As[k][ty * 4 + i];
#pragma unroll
            for (int j = 0; j < 4; j++) b[j] = Bs[k][tx * 4 + j];
#pragma unroll
            for (int i = 0; i < 4; i++)
#pragma unroll
                for (int j = 0; j < 4; j++)
                    acc[i][j] = fmaf(a[i], b[j], acc[i][j]);
        }
        __syncthreads();
    }

#pragma unroll
    for (int i = 0; i < 4; i++) {
        int gm = m0 + ty * 4 + i;
        if (gm >= M) continue;
#pragma unroll
        for (int j = 0; j < 4; j++) {
            int gn = n0 + tx * 4 + j;
            if (gn >= N) continue;
            float v = acc[i][j] + bias[gn];
            if (ACT == ACT_ELU)  v = (v > 0.f) ? v : expm1f(v);
            if (ACT == ACT_TANH) v = tanhf(v);
            C[(size_t)gm * N + gn] = v;
        }
    }
}

// ---------------- latent path ----------------------------------------------
__global__ void bmat_kernel(const float* __restrict__ W, float* __restrict__ bmat)
{
    int t = threadIdx.x;
    int i = t >> 4, j = t & 15;
    bmat[t] = (j > i) ? W[t] * (float)(j - i) : 0.f;
}

// Fused: logvar = h2 @ logvar_w + b; eps = exp(lv/2)*noise; triangular solve.
// One warp per batch row.
__global__ void __launch_bounds__(256)
logvar_z_kernel(const float* __restrict__ h2,
                const float* __restrict__ lw, const float* __restrict__ lb,
                const float* __restrict__ W,
                const float* __restrict__ noise,
                float* __restrict__ lv_o, float* __restrict__ z_o,
                float* __restrict__ bz_o)
{
    const int lane = threadIdx.x & 31;
    const int b = blockIdx.x * 8 + (threadIdx.x >> 5);

    float acc[D];
#pragma unroll
    for (int j = 0; j < D; j++) acc[j] = 0.f;

#pragma unroll
    for (int tt = 0; tt < 10; tt++) {
        int k = lane + tt * 32;
        if (k < H2) {
            float hv = h2[(size_t)b * H2 + k];
#pragma unroll
            for (int j4 = 0; j4 < 4; j4++) {
                float4 w = *(const float4*)&lw[(size_t)k * D + j4 * 4];
                acc[j4 * 4 + 0] = fmaf(hv, w.x, acc[j4 * 4 + 0]);
                acc[j4 * 4 + 1] = fmaf(hv, w.y, acc[j4 * 4 + 1]);
                acc[j4 * 4 + 2] = fmaf(hv, w.z, acc[j4 * 4 + 2]);
                acc[j4 * 4 + 3] = fmaf(hv, w.w, acc[j4 * 4 + 3]);
            }
        }
    }
#pragma unroll
    for (int off = 16; off > 0; off >>= 1)
#pragma unroll
        for (int j = 0; j < D; j++)
            acc[j] += __shfl_xor_sync(0xFFFFFFFF, acc[j], off);

#pragma unroll
    for (int j = 0; j < D; j++) acc[j] += lb[j];

    float eps[D], zz[D], bz[D];
#pragma unroll
    for (int j = 0; j < D; j++)
        eps[j] = expf(0.5f * acc[j]) * noise[(size_t)b * D + j];
#pragma unroll
    for (int j = 0; j < D; j++) {
        float s = 0.f;
#pragma unroll
        for (int i = 0; i < D; i++)
            if (i < j) s = fmaf(zz[i], W[i * D + j] * (float)(j - i), s);
        bz[j] = s;
        zz[j] = eps[j] + s;
    }
    if (lane < D) {
        lv_o[(size_t)b * D + lane] = acc[lane];
        z_o [(size_t)b * D + lane] = zz[lane];
        bz_o[(size_t)b * D + lane] = bz[lane];
    }
}

// ---------------- launch -----------------------------------------------------
extern "C" void kernel_launch(void* const* d_in, const int* in_sizes, int n_in,
                              void* d_out, int out_size)
{
    (void)in_sizes; (void)n_in; (void)out_size;

    const float* x        = (const float*)d_in[0];
    const float* noise    = (const float*)d_in[1];
    const float* enc_w1   = (const float*)d_in[2];
    const float* enc_b1   = (const float*)d_in[3];
    const float* enc_w2   = (const float*)d_in[4];
    const float* enc_b2   = (const float*)d_in[5];
    const float* logvar_w = (const float*)d_in[6];
    const float* logvar_b = (const float*)d_in[7];
    const float* W        = (const float*)d_in[8];
    const float* dec_w1   = (const float*)d_in[9];
    const float* dec_b1   = (const float*)d_in[10];
    const float* dec_w2   = (const float*)d_in[11];
    const float* dec_b2   = (const float*)d_in[12];
    const float* dec_w3   = (const float*)d_in[13];
    const float* dec_b3   = (const float*)d_in[14];

    float* out  = (float*)d_out;
    float* z_o  = out;
    float* lv_o = out + BATCH * D;
    float* bz_o = out + 2 * BATCH * D;
    float* bm_o = out + 3 * BATCH * D;
    float* xh_o = out + 3 * BATCH * D + D * D;

    float *h1, *h2, *g1, *g2, *ws;
    cudaGetSymbolAddress((void**)&h1, g_h1);
    cudaGetSymbolAddress((void**)&h2, g_h2);
    cudaGetSymbolAddress((void**)&g1, g_g1);
    cudaGetSymbolAddress((void**)&g2, g_g2);
    cudaGetSymbolAddress((void**)&ws, g_ws);
    __nv_bfloat16 *xh, *xl, *w1h, *w1l, *h1h, *h1l, *w2h, *w2l;
    __nv_bfloat16 *g1h, *g1l, *dw2h, *dw2l, *g2h, *g2l, *w3h, *w3l;
    cudaGetSymbolAddress((void**)&xh,   g_xh);
    cudaGetSymbolAddress((void**)&xl,   g_xl);
    cudaGetSymbolAddress((void**)&w1h,  g_w1h);
    cudaGetSymbolAddress((void**)&w1l,  g_w1l);
    cudaGetSymbolAddress((void**)&h1h,  g_h1h);
    cudaGetSymbolAddress((void**)&h1l,  g_h1l);
    cudaGetSymbolAddress((void**)&w2h,  g_w2h);
    cudaGetSymbolAddress((void**)&w2l,  g_w2l);
    cudaGetSymbolAddress((void**)&g1h,  g_g1h);
    cudaGetSymbolAddress((void**)&g1l,  g_g1l);
    cudaGetSymbolAddress((void**)&dw2h, g_dw2h);
    cudaGetSymbolAddress((void**)&dw2l, g_dw2l);
    cudaGetSymbolAddress((void**)&g2h,  g_g2h);
    cudaGetSymbolAddress((void**)&g2l,  g_g2l);
    cudaGetSymbolAddress((void**)&w3h,  g_w3h);
    cudaGetSymbolAddress((void**)&w3l,  g_w3l);

    cudaFuncSetAttribute(mma_gemm_big<ACT_RAW>,
                         cudaFuncAttributeMaxDynamicSharedMemorySize, SMEM_BYTES);
    cudaFuncSetAttribute(mma_gemm_big<ACT_ELU>,
                         cudaFuncAttributeMaxDynamicSharedMemorySize, SMEM_BYTES);
    cudaFuncSetAttribute(mma_gemm_big<ACT_TANH>,
                         cudaFuncAttributeMaxDynamicSharedMemorySize, SMEM_BYTES);

    dim3 blk(256);

    // ---- operand prep (hi/lo bf16 splits, zero-padded)
    split_bf16_v4<<<dim3(IMG / 1024, BATCH), blk>>>(x, xh, xl, BATCH, IMG, IMG);
    split_bf16_v4<<<dim3(1, IMG), blk>>>(enc_w1, w1h, w1l, IMG, H1, W1N);
    split_bf16_v4<<<dim3(1, H1K), blk>>>(enc_w2, w2h, w2l, H1, H2, H2N);
    split_bf16_v4<<<dim3(1, H2K), blk>>>(dec_w2, dw2h, dw2l, H2, H2, H2N);
    split_bf16_v4<<<dim3(IMG / 1024, H2K), blk>>>(dec_w3, w3h, w3l, H2, IMG, IMG);

    // ---- enc1: split-K=4 tensor GEMM + combine
    {
        int kt = IMG / (KSLICES * TBK);           // 216
        mma_gemm_big<ACT_RAW><<<dim3(W1N / TBN, BATCH / TBM, KSLICES), 128, SMEM_BYTES>>>(
            xh, xl, IMG, w1h, w1l, W1N, nullptr, ws, W1N, W1N, kt, kt);
    }
    reduce_elu<<<(BATCH * H1 + 255) / 256, blk>>>(ws, enc_b1, h1);

    // ---- enc2 (tensor)
    split_bf16_v4<<<dim3(1, BATCH), blk>>>(h1, h1h, h1l, BATCH, H1, H1K);
    mma_gemm_big<ACT_ELU><<<dim3(H2N / TBN, BATCH / TBM, 1), 128, SMEM_BYTES>>>(
        h1h, h1l, H1K, w2h, w2l, H2N, enc_b2, h2, H2, H2, H1K / TBK, H1K / TBK);

    // ---- logvar + latent solve (fused) + Bmat
    logvar_z_kernel<<<BATCH / 8, blk>>>(h2, logvar_w, logvar_b, W, noise,
                                        lv_o, z_o, bz_o);
    bmat_kernel<<<1, 256>>>(W, bm_o);

    // ---- decoder
    gemm_bias_act<ACT_ELU><<<dim3((H2 + SBN - 1) / SBN, BATCH / SBM), blk>>>(
        z_o, dec_w1, dec_b1, g1, BATCH, H2, D);
    split_bf16_v4<<<dim3(1, BATCH), blk>>>(g1, g1h, g1l, BATCH, H2, H2K);
    mma_gemm_big<ACT_ELU><<<dim3(H2N / TBN, BATCH / TBM, 1), 128, SMEM_BYTES>>>(
        g1h, g1l, H2K, dw2h, dw2l, H2N, dec_b2, g2, H2, H2, H2K / TBK, H2K / TBK);
    split_bf16_v4<<<dim3(1, BATCH), blk>>>(g2, g2h, g2l, BATCH, H2, H2K);
    mma_gemm_big<ACT_TANH><<<dim3(IMG / TBN, BATCH / TBM, 1), 128, SMEM_BYTES>>>(
        g2h, g2l, H2K, w3h, w3l, IMG, dec_b3, xh_o, IMG, IMG, H2K / TBK, H2K / TBK);
}

// round 7
// speedup vs baseline: 3.7313x; 1.2628x over previous
#include <cuda_runtime.h>
#include <cuda_bf16.h>
#include <math.h>
#include <stdint.h>

// ---------------------------------------------------------------------------
// VAE forward. Round 7: 3-product bf16 split (hh+hl+lh), split-K=4 on enc1/
// enc2/dec2, fused split-emitting epilogues (h1, g1, g2), fused logvar+solve
// consuming enc2 partials. mma.sync 64x64 warp tiles, 3-stage cp.async.
// ---------------------------------------------------------------------------

#define BATCH 1024
#define IMG   27648
#define H1    900
#define H2    300
#define D     16

#define W1N 1024           // enc1 N padded
#define H1K 960            // h1 K padded (enc2 A)
#define H2N 384            // enc2/dec2 N padded (GEMM tiles)
#define H2K 320            // g1/g2 K padded (dec2/dec3 A)
#define KSLICES 4

enum { ACT_TANH = 2, ACT_RAW = 3 };

// ---------------- scratch ----------------------------------------------------
__device__ float g_h2unused[1];  // (h2 fp32 no longer materialized)
__device__ float g_ws[KSLICES * BATCH * W1N];   // split-K partials (reused 3x)

__device__ __align__(16) __nv_bfloat16 g_xh[(size_t)BATCH * IMG];
__device__ __align__(16) __nv_bfloat16 g_xl[(size_t)BATCH * IMG];
__device__ __align__(16) __nv_bfloat16 g_w1h[(size_t)IMG * W1N];
__device__ __align__(16) __nv_bfloat16 g_w1l[(size_t)IMG * W1N];
__device__ __align__(16) __nv_bfloat16 g_h1h[(size_t)BATCH * H1K];
__device__ __align__(16) __nv_bfloat16 g_h1l[(size_t)BATCH * H1K];
__device__ __align__(16) __nv_bfloat16 g_w2h[(size_t)H1K * H2N];
__device__ __align__(16) __nv_bfloat16 g_w2l[(size_t)H1K * H2N];
__device__ __align__(16) __nv_bfloat16 g_g1h[(size_t)BATCH * H2K];
__device__ __align__(16) __nv_bfloat16 g_g1l[(size_t)BATCH * H2K];
__device__ __align__(16) __nv_bfloat16 g_dw2h[(size_t)H2K * H2N];
__device__ __align__(16) __nv_bfloat16 g_dw2l[(size_t)H2K * H2N];
__device__ __align__(16) __nv_bfloat16 g_g2h[(size_t)BATCH * H2K];
__device__ __align__(16) __nv_bfloat16 g_g2l[(size_t)BATCH * H2K];
__device__ __align__(16) __nv_bfloat16 g_w3h[(size_t)H2K * IMG];
__device__ __align__(16) __nv_bfloat16 g_w3l[(size_t)H2K * IMG];

// ---------------- fp32 -> (hi, lo) bf16 split with 2D zero padding ---------
__global__ void split_bf16_v4(const float* __restrict__ src,
                              __nv_bfloat16* __restrict__ hi,
                              __nv_bfloat16* __restrict__ lo,
                              int src_rows, int src_cols, int dst_cols)
{
    int c = (blockIdx.x * 256 + threadIdx.x) * 4;
    int r = blockIdx.y;
    if (c >= dst_cols) return;
    float v[4];
    if (r < src_rows && c + 3 < src_cols) {
        float4 f = *(const float4*)&src[(size_t)r * src_cols + c];
        v[0] = f.x; v[1] = f.y; v[2] = f.z; v[3] = f.w;
    } else {
#pragma unroll
        for (int i = 0; i < 4; i++)
            v[i] = (r < src_rows && c + i < src_cols)
                 ? src[(size_t)r * src_cols + c + i] : 0.f;
    }
    __nv_bfloat16 h4[4], l4[4];
#pragma unroll
    for (int i = 0; i < 4; i++) {
        h4[i] = __float2bfloat16_rn(v[i]);
        l4[i] = __float2bfloat16_rn(v[i] - __bfloat162float(h4[i]));
    }
    size_t o = (size_t)r * dst_cols + c;
    *(uint64_t*)&hi[o] = *(uint64_t*)h4;
    *(uint64_t*)&lo[o] = *(uint64_t*)l4;
}

// ---------------- tensor-core GEMM (bf16x3, 64x64 warp tiles) --------------
#define TBM 128
#define TBN 128
#define TBK 32
#define ASTR 40
#define BSTR 136
#define NSTG 3

#define A_BYTES (TBM * ASTR * 2)
#define B_BYTES (TBK * BSTR * 2)
#define STAGE_BYTES (2 * A_BYTES + 2 * B_BYTES)
#define SMEM_BYTES (NSTG * STAGE_BYTES)

__device__ __forceinline__ void cp16(void* s, const void* g)
{
    uint32_t sa = (uint32_t)__cvta_generic_to_shared(s);
    asm volatile("cp.async.cg.shared.global [%0], [%1], 16;\n" :: "r"(sa), "l"(g));
}

__device__ __forceinline__ void ldsm_x4(uint32_t* r, const void* p)
{
    uint32_t a = (uint32_t)__cvta_generic_to_shared(p);
    asm volatile("ldmatrix.sync.aligned.m8n8.x4.shared.b16 {%0,%1,%2,%3}, [%4];\n"
                 : "=r"(r[0]), "=r"(r[1]), "=r"(r[2]), "=r"(r[3]) : "r"(a));
}

__device__ __forceinline__ void ldsm_x4_t(uint32_t* r, const void* p)
{
    uint32_t a = (uint32_t)__cvta_generic_to_shared(p);
    asm volatile("ldmatrix.sync.aligned.m8n8.x4.trans.shared.b16 {%0,%1,%2,%3}, [%4];\n"
                 : "=r"(r[0]), "=r"(r[1]), "=r"(r[2]), "=r"(r[3]) : "r"(a));
}

__device__ __forceinline__ void mma16816(float* c, const uint32_t* a, const uint32_t* b)
{
    asm volatile(
        "mma.sync.aligned.m16n8k16.row.col.f32.bf16.bf16.f32 "
        "{%0,%1,%2,%3}, {%4,%5,%6,%7}, {%8,%9}, {%0,%1,%2,%3};\n"
        : "+f"(c[0]), "+f"(c[1]), "+f"(c[2]), "+f"(c[3])
        : "r"(a[0]), "r"(a[1]), "r"(a[2]), "r"(a[3]), "r"(b[0]), "r"(b[1]));
}

// C = Ah@Bh + Ah@Bl + Al@Bh (+ bias/tanh); blockIdx.z = K slice (RAW).
template <int ACT>
__global__ void __launch_bounds__(128, 2)
mma_gemm_big(const __nv_bfloat16* __restrict__ Ah, const __nv_bfloat16* __restrict__ Al,
             int lda,
             const __nv_bfloat16* __restrict__ Bh, const __nv_bfloat16* __restrict__ Bl,
             int ldb,
             const float* __restrict__ bias, float* __restrict__ C, int ldc,
             int Nreal, int KT, int kslice_kt)
{
    extern __shared__ char smem[];
    __nv_bfloat16 *sAh[NSTG], *sAl[NSTG], *sBh[NSTG], *sBl[NSTG];
#pragma unroll
    for (int s = 0; s < NSTG; s++) {
        char* base = smem + s * STAGE_BYTES;
        sAh[s] = (__nv_bfloat16*)(base);
        sAl[s] = (__nv_bfloat16*)(base + A_BYTES);
        sBh[s] = (__nv_bfloat16*)(base + 2 * A_BYTES);
        sBl[s] = (__nv_bfloat16*)(base + 2 * A_BYTES + B_BYTES);
    }

    const int t    = threadIdx.x;
    const int lane = t & 31;
    const int wid  = t >> 5;
    const int wm   = wid & 1;
    const int wn   = wid >> 1;
    const int m0   = blockIdx.y * TBM;
    const int n0   = blockIdx.x * TBN;
    const int kofs = blockIdx.z * kslice_kt * TBK;

    float acc[4][8][4];
#pragma unroll
    for (int i = 0; i < 4; i++)
#pragma unroll
        for (int j = 0; j < 8; j++)
#pragma unroll
            for (int q = 0; q < 4; q++) acc[i][j][q] = 0.f;

    auto load_stage = [&](int s, int kt) {
        const int k0 = kofs + kt * TBK;
#pragma unroll
        for (int i = 0; i < 4; i++) {
            int idx = t + i * 128;
            int row = idx >> 2, seg = idx & 3;
            int so = row * ASTR + seg * 8;
            size_t go = (size_t)(m0 + row) * lda + k0 + seg * 8;
            cp16(&sAh[s][so], &Ah[go]);
            cp16(&sAl[s][so], &Al[go]);
        }
#pragma unroll
        for (int i = 0; i < 4; i++) {
            int idx = t + i * 128;
            int row = idx >> 4, seg = idx & 15;
            int so = row * BSTR + seg * 8;
            size_t go = (size_t)(k0 + row) * ldb + n0 + seg * 8;
            cp16(&sBh[s][so], &Bh[go]);
            cp16(&sBl[s][so], &Bl[go]);
        }
        asm volatile("cp.async.commit_group;\n");
    };

    load_stage(0, 0);
    if (KT > 1) load_stage(1, 1);

    int slot = 0;
    for (int kt = 0; kt < KT; kt++) {
        if (kt < KT - 1) asm volatile("cp.async.wait_group 1;\n" ::: "memory");
        else             asm volatile("cp.async.wait_group 0;\n" ::: "memory");
        __syncthreads();
        if (kt + 2 < KT) {
            int ns = slot + 2; if (ns >= NSTG) ns -= NSTG;
            load_stage(ns, kt + 2);
        }

#pragma unroll
        for (int ks = 0; ks < 2; ks++) {
            uint32_t afh[4][4], afl[4][4];
#pragma unroll
            for (int mt = 0; mt < 4; mt++) {
                int r = wm * 64 + mt * 16 + (lane & 15);
                int c = ks * 16 + ((lane >> 4) << 3);
                ldsm_x4(afh[mt], &sAh[slot][r * ASTR + c]);
                ldsm_x4(afl[mt], &sAl[slot][r * ASTR + c]);
            }
            uint32_t bfh[8][2], bfl[8][2];
#pragma unroll
            for (int np = 0; np < 4; np++) {
                int r = ks * 16 + (lane & 15);
                int c = wn * 64 + np * 16 + ((lane >> 4) << 3);
                uint32_t rh[4], rl[4];
                ldsm_x4_t(rh, &sBh[slot][r * BSTR + c]);
                ldsm_x4_t(rl, &sBl[slot][r * BSTR + c]);
                bfh[np * 2][0] = rh[0]; bfh[np * 2][1] = rh[1];
                bfh[np * 2 + 1][0] = rh[2]; bfh[np * 2 + 1][1] = rh[3];
                bfl[np * 2][0] = rl[0]; bfl[np * 2][1] = rl[1];
                bfl[np * 2 + 1][0] = rl[2]; bfl[np * 2 + 1][1] = rl[3];
            }
#pragma unroll
            for (int mt = 0; mt < 4; mt++)
#pragma unroll
                for (int nt = 0; nt < 8; nt++) {
                    mma16816(acc[mt][nt], afh[mt], bfh[nt]);   // hh
                    mma16816(acc[mt][nt], afh[mt], bfl[nt]);   // hl
                    mma16816(acc[mt][nt], afl[mt], bfh[nt]);   // lh
                }
        }
        slot++; if (slot >= NSTG) slot -= NSTG;
    }

    float* Cz = C + (size_t)blockIdx.z * ((size_t)BATCH * ldc);
#pragma unroll
    for (int mt = 0; mt < 4; mt++) {
#pragma unroll
        for (int nt = 0; nt < 8; nt++) {
            int col = n0 + wn * 64 + nt * 8 + (lane & 3) * 2;
            if (col >= Nreal) continue;
            float b0 = 0.f, b1 = 0.f;
            if (ACT != ACT_RAW) { b0 = bias[col]; b1 = bias[col + 1]; }
#pragma unroll
            for (int h = 0; h < 2; h++) {
                int row = m0 + wm * 64 + mt * 16 + (lane >> 2) + h * 8;
                float v0 = acc[mt][nt][2 * h + 0] + b0;
                float v1 = acc[mt][nt][2 * h + 1] + b1;
                if (ACT == ACT_TANH) { v0 = tanhf(v0); v1 = tanhf(v1); }
                *(float2*)&Cz[(size_t)row * ldc + col] = make_float2(v0, v1);
            }
        }
    }
}

// ---------------- split-K combine -> elu -> bf16 hi/lo ---------------------
// out[m, n<Npad] = split(elu(sum_z ws[z][m][n] + bias[n])) (0 for n>=Nreal)
__global__ void reduce_elu_split(const float* __restrict__ ws, int ldw,
                                 const float* __restrict__ bias,
                                 __nv_bfloat16* __restrict__ hi,
                                 __nv_bfloat16* __restrict__ lo,
                                 int Nreal, int Npad, int total)
{
    int i = blockIdx.x * 256 + threadIdx.x;
    if (i >= total) return;
    int m = i / Npad, n = i - m * Npad;
    float v = 0.f;
    if (n < Nreal) {
        size_t o = (size_t)m * ldw + n;
        v = bias[n];
#pragma unroll
        for (int z = 0; z < KSLICES; z++)
            v += ws[(size_t)z * BATCH * ldw + o];
        v = v > 0.f ? v : expm1f(v);
    }
    __nv_bfloat16 h = __float2bfloat16_rn(v);
    hi[i] = h;
    lo[i] = __float2bfloat16_rn(v - __bfloat162float(h));
}

// ---------------- fp32 SIMT GEMM -> elu -> bf16 hi/lo (dec1, K=16) ---------
#define SBM 64
#define SBN 64

__global__ void __launch_bounds__(256)
gemm_elu_split(const float* __restrict__ A, const float* __restrict__ B,
               const float* __restrict__ bias,
               __nv_bfloat16* __restrict__ hi, __nv_bfloat16* __restrict__ lo,
               int M, int Nout, int Nreal, int K)
{
    __shared__ float As[16][SBM + 1];
    __shared__ float Bs[16][SBN];

    const int t  = threadIdx.x;
    const int tx = t & 15;
    const int ty = t >> 4;
    const int n0 = blockIdx.x * SBN;
    const int m0 = blockIdx.y * SBM;

    float acc[4][4];
#pragma unroll
    for (int i = 0; i < 4; i++)
#pragma unroll
        for (int j = 0; j < 4; j++) acc[i][j] = 0.f;

    for (int k0 = 0; k0 < K; k0 += 16) {
#pragma unroll
        for (int i = 0; i < 4; i++) {
            int e = t + i * 256;
            int c = e & 15, r = e >> 4;
            int gm = m0 + r, gk = k0 + c;
            As[c][r] = (gm < M && gk < K) ? A[(size_t)gm * K + gk] : 0.f;
        }
#pragma unroll
        for (int i = 0; i < 4; i++) {
            int e = t + i * 256;
            int n = e & 63, kk = e >> 6;
            int gk = k0 + kk, gn = n0 + n;
            Bs[kk][n] = (gk < K && gn < Nreal) ? B[(size_t)gk * Nreal + gn] : 0.f;
        }
        __syncthreads();
#pragma unroll
        for (int k = 0; k < 16; k++) {
            float a[4], b[4];
#pragma unroll
            for (int i = 0; i < 4; i++) a[i] = As[k][ty * 4 + i];
#pragma unroll
            for (int j = 0; j < 4; j++) b[j] = Bs[k][tx * 4 + j];
#pragma unroll
            for (int i = 0; i < 4; i++)
#pragma unroll
                for (int j = 0; j < 4; j++)
                    acc[i][j] = fmaf(a[i], b[j], acc[i][j]);
        }
        __syncthreads();
    }

#pragma unroll
    for (int i = 0; i < 4; i++) {
        int gm = m0 + ty * 4 + i;
        if (gm >= M) continue;
#pragma unroll
        for (int j = 0; j < 4; j++) {
            int gn = n0 + tx * 4 + j;
            if (gn >= Nout) continue;
            float v = 0.f;
            if (gn < Nreal) {
                v = acc[i][j] + bias[gn];
                v = (v > 0.f) ? v : expm1f(v);
            }
            __nv_bfloat16 h = __float2bfloat16_rn(v);
            size_t o = (size_t)gm * Nout + gn;
            hi[o] = h;
            lo[o] = __float2bfloat16_rn(v - __bfloat162float(h));
        }
    }
}

// ---------------- latent path ----------------------------------------------
__global__ void bmat_kernel(const float* __restrict__ W, float* __restrict__ bmat)
{
    int t = threadIdx.x;
    int i = t >> 4, j = t & 15;
    bmat[t] = (j > i) ? W[t] * (float)(j - i) : 0.f;
}

// Fused: h2 = elu(sum_z ws2[z] + b2); logvar = h2 @ lw + lb; eps; tri-solve.
// One warp per batch row; ws2 partials over H2N-wide rows.
__global__ void __launch_bounds__(256)
logvar_z_kernel(const float* __restrict__ ws2, int ldw,
                const float* __restrict__ b2,
                const float* __restrict__ lw, const float* __restrict__ lb,
                const float* __restrict__ W,
                const float* __restrict__ noise,
                float* __restrict__ lv_o, float* __restrict__ z_o,
                float* __restrict__ bz_o)
{
    const int lane = threadIdx.x & 31;
    const int b = blockIdx.x * 8 + (threadIdx.x >> 5);

    float acc[D];
#pragma unroll
    for (int j = 0; j < D; j++) acc[j] = 0.f;

#pragma unroll
    for (int tt = 0; tt < 10; tt++) {
        int k = lane + tt * 32;
        if (k < H2) {
            size_t o = (size_t)b * ldw + k;
            float hv = b2[k];
#pragma unroll
            for (int z = 0; z < KSLICES; z++)
                hv += ws2[(size_t)z * BATCH * ldw + o];
            hv = hv > 0.f ? hv : expm1f(hv);
#pragma unroll
            for (int j4 = 0; j4 < 4; j4++) {
                float4 w = *(const float4*)&lw[(size_t)k * D + j4 * 4];
                acc[j4 * 4 + 0] = fmaf(hv, w.x, acc[j4 * 4 + 0]);
                acc[j4 * 4 + 1] = fmaf(hv, w.y, acc[j4 * 4 + 1]);
                acc[j4 * 4 + 2] = fmaf(hv, w.z, acc[j4 * 4 + 2]);
                acc[j4 * 4 + 3] = fmaf(hv, w.w, acc[j4 * 4 + 3]);
            }
        }
    }
#pragma unroll
    for (int off = 16; off > 0; off >>= 1)
#pragma unroll
        for (int j = 0; j < D; j++)
            acc[j] += __shfl_xor_sync(0xFFFFFFFF, acc[j], off);

#pragma unroll
    for (int j = 0; j < D; j++) acc[j] += lb[j];

    float eps[D], zz[D], bz[D];
#pragma unroll
    for (int j = 0; j < D; j++)
        eps[j] = expf(0.5f * acc[j]) * noise[(size_t)b * D + j];
#pragma unroll
    for (int j = 0; j < D; j++) {
        float s = 0.f;
#pragma unroll
        for (int i = 0; i < D; i++)
            if (i < j) s = fmaf(zz[i], W[i * D + j] * (float)(j - i), s);
        bz[j] = s;
        zz[j] = eps[j] + s;
    }
    if (lane < D) {
        lv_o[(size_t)b * D + lane] = acc[lane];
        z_o [(size_t)b * D + lane] = zz[lane];
        bz_o[(size_t)b * D + lane] = bz[lane];
    }
}

// ---------------- launch -----------------------------------------------------
extern "C" void kernel_launch(void* const* d_in, const int* in_sizes, int n_in,
                              void* d_out, int out_size)
{
    (void)in_sizes; (void)n_in; (void)out_size;

    const float* x        = (const float*)d_in[0];
    const float* noise    = (const float*)d_in[1];
    const float* enc_w1   = (const float*)d_in[2];
    const float* enc_b1   = (const float*)d_in[3];
    const float* enc_w2   = (const float*)d_in[4];
    const float* enc_b2   = (const float*)d_in[5];
    const float* logvar_w = (const float*)d_in[6];
    const float* logvar_b = (const float*)d_in[7];
    const float* W        = (const float*)d_in[8];
    const float* dec_w1   = (const float*)d_in[9];
    const float* dec_b1   = (const float*)d_in[10];
    const float* dec_w2   = (const float*)d_in[11];
    const float* dec_b2   = (const float*)d_in[12];
    const float* dec_w3   = (const float*)d_in[13];
    const float* dec_b3   = (const float*)d_in[14];

    float* out  = (float*)d_out;
    float* z_o  = out;
    float* lv_o = out + BATCH * D;
    float* bz_o = out + 2 * BATCH * D;
    float* bm_o = out + 3 * BATCH * D;
    float* xh_o = out + 3 * BATCH * D + D * D;

    float* ws;
    cudaGetSymbolAddress((void**)&ws, g_ws);
    __nv_bfloat16 *xh, *xl, *w1h, *w1l, *h1h, *h1l, *w2h, *w2l;
    __nv_bfloat16 *g1h, *g1l, *dw2h, *dw2l, *g2h, *g2l, *w3h, *w3l;
    cudaGetSymbolAddress((void**)&xh,   g_xh);
    cudaGetSymbolAddress((void**)&xl,   g_xl);
    cudaGetSymbolAddress((void**)&w1h,  g_w1h);
    cudaGetSymbolAddress((void**)&w1l,  g_w1l);
    cudaGetSymbolAddress((void**)&h1h,  g_h1h);
    cudaGetSymbolAddress((void**)&h1l,  g_h1l);
    cudaGetSymbolAddress((void**)&w2h,  g_w2h);
    cudaGetSymbolAddress((void**)&w2l,  g_w2l);
    cudaGetSymbolAddress((void**)&g1h,  g_g1h);
    cudaGetSymbolAddress((void**)&g1l,  g_g1l);
    cudaGetSymbolAddress((void**)&dw2h, g_dw2h);
    cudaGetSymbolAddress((void**)&dw2l, g_dw2l);
    cudaGetSymbolAddress((void**)&g2h,  g_g2h);
    cudaGetSymbolAddress((void**)&g2l,  g_g2l);
    cudaGetSymbolAddress((void**)&w3h,  g_w3h);
    cudaGetSymbolAddress((void**)&w3l,  g_w3l);

    cudaFuncSetAttribute(mma_gemm_big<ACT_RAW>,
                         cudaFuncAttributeMaxDynamicSharedMemorySize, SMEM_BYTES);
    cudaFuncSetAttribute(mma_gemm_big<ACT_TANH>,
                         cudaFuncAttributeMaxDynamicSharedMemorySize, SMEM_BYTES);

    dim3 blk(256);

    // ---- operand prep (hi/lo bf16 splits, zero-padded)
    split_bf16_v4<<<dim3(IMG / 1024, BATCH), blk>>>(x, xh, xl, BATCH, IMG, IMG);
    split_bf16_v4<<<dim3(1, IMG), blk>>>(enc_w1, w1h, w1l, IMG, H1, W1N);
    split_bf16_v4<<<dim3(1, H1K), blk>>>(enc_w2, w2h, w2l, H1, H2, H2N);
    split_bf16_v4<<<dim3(1, H2K), blk>>>(dec_w2, dw2h, dw2l, H2, H2, H2N);
    split_bf16_v4<<<dim3(IMG / 1024, H2K), blk>>>(dec_w3, w3h, w3l, H2, IMG, IMG);

    // ---- enc1: split-K=4 -> partials -> combine+elu+split (h1 hi/lo, pad 960)
    {
        int kt = IMG / (KSLICES * TBK);
        mma_gemm_big<ACT_RAW><<<dim3(W1N / TBN, BATCH / TBM, KSLICES), 128, SMEM_BYTES>>>(
            xh, xl, IMG, w1h, w1l, W1N, nullptr, ws, W1N, W1N, kt, kt);
    }
    reduce_elu_split<<<(BATCH * H1K + 255) / 256, blk>>>(
        ws, W1N, enc_b1, h1h, h1l, H1, H1K, BATCH * H1K);

    // ---- enc2: split-K=4 -> partials (H2N wide)
    {
        int kt = H1K / (KSLICES * TBK);           // 7.5 -> must divide: 960/(4*32)=7.5
        // H1K=960 not divisible by 4*32=128 -> use KSLICES slices of unequal kt?
        // Use 3 slices of 10 kt instead (960/32=30 kt, 3 slices x 10).
        (void)kt;
    }
    mma_gemm_big<ACT_RAW><<<dim3(H2N / TBN, BATCH / TBM, 3), 128, SMEM_BYTES>>>(
        h1h, h1l, H1K, w2h, w2l, H2N, nullptr, ws, H2N, H2N, 10, 10);
    // zero slice 3 partials? logvar kernel sums KSLICES=4 -> sum only 3 here:
    // handled by summing slices 0..2 plus slice 3 aliasing zero... instead we
    // simply pass a 3-slice-aware reduction via templated loop below.

    // ---- logvar + latent solve (sums 3 enc2 partials) + Bmat
    // (logvar_z_kernel sums KSLICES=4 slices; slice 3 would read stale data.
    //  To keep it correct we zero slice 3 region first with a cheap kernel.)
    cudaMemsetAsync(ws + (size_t)3 * BATCH * H2N, 0,
                    (size_t)BATCH * H2N * sizeof(float));
    logvar_z_kernel<<<BATCH / 8, blk>>>(ws, H2N, enc_b2, logvar_w, logvar_b,
                                        W, noise, lv_o, z_o, bz_o);
    bmat_kernel<<<1, 256>>>(W, bm_o);

    // ---- dec1 (K=16, SIMT) -> g1 hi/lo (pad 320)
    gemm_elu_split<<<dim3(H2K / SBN, BATCH / SBM), blk>>>(
        z_o, dec_w1, dec_b1, g1h, g1l, BATCH, H2K, H2, D);

    // ---- dec2: split-K (320/32=10 kt -> 2 slices of 5) -> combine (g2 hi/lo)
    mma_gemm_big<ACT_RAW><<<dim3(H2N / TBN, BATCH / TBM, 2), 128, SMEM_BYTES>>>(
        g1h, g1l, H2K, dw2h, dw2l, H2N, nullptr, ws, H2N, H2N, 5, 5);
    cudaMemsetAsync(ws + (size_t)2 * BATCH * H2N, 0,
                    (size_t)2 * BATCH * H2N * sizeof(float));
    reduce_elu_split<<<(BATCH * H2K + 255) / 256, blk>>>(
        ws, H2N, dec_b2, g2h, g2l, H2, H2K, BATCH * H2K);

    // ---- dec3 (tanh)
    mma_gemm_big<ACT_TANH><<<dim3(IMG / TBN, BATCH / TBM, 1), 128, SMEM_BYTES>>>(
        g2h, g2l, H2K, w3h, w3l, IMG, dec_b3, xh_o, IMG, IMG, H2K / TBK, H2K / TBK);
}

// round 8
// speedup vs baseline: 4.7796x; 1.2810x over previous
#include <cuda_runtime.h>
#include <cuda_fp16.h>
#include <math.h>
#include <stdint.h>

// ---------------------------------------------------------------------------
// VAE forward. Round 8: fp16 hi/lo splits. enc1 = 2-product (A split, B single
// fp16); enc2/dec2/dec3 = 3-product fp16. Fused logvar+solve+dec1+bmat kernel,
// templated split-K reduce (no memsets). mma.sync 64x64 warp tiles.
// ---------------------------------------------------------------------------

#define BATCH 1024
#define IMG   27648
#define H1    900
#define H2    300
#define D     16

#define W1N 1024           // enc1 N padded
#define H1K 960            // h1 K padded (enc2 A)
#define H2N 384            // enc2/dec2 N padded
#define H2K 320            // g1/g2 K padded (dec2/dec3 A)

enum { ACT_TANH = 2, ACT_RAW = 3 };

// ---------------- scratch ----------------------------------------------------
__device__ float g_ws[4 * BATCH * W1N];          // split-K partials (reused)

__device__ __align__(16) __half g_xh[(size_t)BATCH * IMG];
__device__ __align__(16) __half g_xl[(size_t)BATCH * IMG];
__device__ __align__(16) __half g_w1h[(size_t)IMG * W1N];
__device__ __align__(16) __half g_h1h[(size_t)BATCH * H1K];
__device__ __align__(16) __half g_h1l[(size_t)BATCH * H1K];
__device__ __align__(16) __half g_w2h[(size_t)H1K * H2N];
__device__ __align__(16) __half g_w2l[(size_t)H1K * H2N];
__device__ __align__(16) __half g_g1h[(size_t)BATCH * H2K];
__device__ __align__(16) __half g_g1l[(size_t)BATCH * H2K];
__device__ __align__(16) __half g_dw2h[(size_t)H2K * H2N];
__device__ __align__(16) __half g_dw2l[(size_t)H2K * H2N];
__device__ __align__(16) __half g_g2h[(size_t)BATCH * H2K];
__device__ __align__(16) __half g_g2l[(size_t)BATCH * H2K];
__device__ __align__(16) __half g_w3h[(size_t)H2K * IMG];
__device__ __align__(16) __half g_w3l[(size_t)H2K * IMG];

// ---------------- fp32 -> fp16 hi/lo split (zero-padded) -------------------
__global__ void split_half_v4(const float* __restrict__ src,
                              __half* __restrict__ hi,
                              __half* __restrict__ lo,
                              int src_rows, int src_cols, int dst_cols)
{
    int c = (blockIdx.x * 256 + threadIdx.x) * 4;
    int r = blockIdx.y;
    if (c >= dst_cols) return;
    float v[4];
    if (r < src_rows && c + 3 < src_cols) {
        float4 f = *(const float4*)&src[(size_t)r * src_cols + c];
        v[0] = f.x; v[1] = f.y; v[2] = f.z; v[3] = f.w;
    } else {
#pragma unroll
        for (int i = 0; i < 4; i++)
            v[i] = (r < src_rows && c + i < src_cols)
                 ? src[(size_t)r * src_cols + c + i] : 0.f;
    }
    __half h4[4], l4[4];
#pragma unroll
    for (int i = 0; i < 4; i++) {
        h4[i] = __float2half_rn(v[i]);
        l4[i] = __float2half_rn(v[i] - __half2float(h4[i]));
    }
    size_t o = (size_t)r * dst_cols + c;
    *(uint64_t*)&hi[o] = *(uint64_t*)h4;
    *(uint64_t*)&lo[o] = *(uint64_t*)l4;
}

// fp32 -> single fp16 (zero-padded)
__global__ void conv_half_v4(const float* __restrict__ src,
                             __half* __restrict__ hi,
                             int src_rows, int src_cols, int dst_cols)
{
    int c = (blockIdx.x * 256 + threadIdx.x) * 4;
    int r = blockIdx.y;
    if (c >= dst_cols) return;
    float v[4];
    if (r < src_rows && c + 3 < src_cols) {
        float4 f = *(const float4*)&src[(size_t)r * src_cols + c];
        v[0] = f.x; v[1] = f.y; v[2] = f.z; v[3] = f.w;
    } else {
#pragma unroll
        for (int i = 0; i < 4; i++)
            v[i] = (r < src_rows && c + i < src_cols)
                 ? src[(size_t)r * src_cols + c + i] : 0.f;
    }
    __half h4[4];
#pragma unroll
    for (int i = 0; i < 4; i++) h4[i] = __float2half_rn(v[i]);
    *(uint64_t*)&hi[(size_t)r * dst_cols + c] = *(uint64_t*)h4;
}

// ---------------- tensor-core GEMM (fp16, 64x64 warp tiles) ----------------
#define TBM 128
#define TBN 128
#define TBK 32
#define ASTR 40
#define BSTR 136
#define NSTG 3

#define A_BYTES (TBM * ASTR * 2)
#define B_BYTES (TBK * BSTR * 2)
#define STAGE_BYTES (2 * A_BYTES + 2 * B_BYTES)
#define SMEM_BYTES (NSTG * STAGE_BYTES)

__device__ __forceinline__ void cp16(void* s, const void* g)
{
    uint32_t sa = (uint32_t)__cvta_generic_to_shared(s);
    asm volatile("cp.async.cg.shared.global [%0], [%1], 16;\n" :: "r"(sa), "l"(g));
}

__device__ __forceinline__ void ldsm_x4(uint32_t* r, const void* p)
{
    uint32_t a = (uint32_t)__cvta_generic_to_shared(p);
    asm volatile("ldmatrix.sync.aligned.m8n8.x4.shared.b16 {%0,%1,%2,%3}, [%4];\n"
                 : "=r"(r[0]), "=r"(r[1]), "=r"(r[2]), "=r"(r[3]) : "r"(a));
}

__device__ __forceinline__ void ldsm_x4_t(uint32_t* r, const void* p)
{
    uint32_t a = (uint32_t)__cvta_generic_to_shared(p);
    asm volatile("ldmatrix.sync.aligned.m8n8.x4.trans.shared.b16 {%0,%1,%2,%3}, [%4];\n"
                 : "=r"(r[0]), "=r"(r[1]), "=r"(r[2]), "=r"(r[3]) : "r"(a));
}

__device__ __forceinline__ void mma16816(float* c, const uint32_t* a, const uint32_t* b)
{
    asm volatile(
        "mma.sync.aligned.m16n8k16.row.col.f32.f16.f16.f32 "
        "{%0,%1,%2,%3}, {%4,%5,%6,%7}, {%8,%9}, {%0,%1,%2,%3};\n"
        : "+f"(c[0]), "+f"(c[1]), "+f"(c[2]), "+f"(c[3])
        : "r"(a[0]), "r"(a[1]), "r"(a[2]), "r"(a[3]), "r"(b[0]), "r"(b[1]));
}

// NPROD==2: C = Ah@Bh + Al@Bh            (A split, B single)
// NPROD==3: C = Ah@Bh + Al@Bh + Ah@Bl    (both split, residual Al@Bl dropped)
template <int ACT, int NPROD>
__global__ void __launch_bounds__(128, 2)
mma_gemm_big(const __half* __restrict__ Ah, const __half* __restrict__ Al,
             int lda,
             const __half* __restrict__ Bh, const __half* __restrict__ Bl,
             int ldb,
             const float* __restrict__ bias, float* __restrict__ C, int ldc,
             int Nreal, int KT, int kslice_kt)
{
    extern __shared__ char smem[];
    __half *sAh[NSTG], *sAl[NSTG], *sBh[NSTG], *sBl[NSTG];
#pragma unroll
    for (int s = 0; s < NSTG; s++) {
        char* base = smem + s * STAGE_BYTES;
        sAh[s] = (__half*)(base);
        sAl[s] = (__half*)(base + A_BYTES);
        sBh[s] = (__half*)(base + 2 * A_BYTES);
        sBl[s] = (__half*)(base + 2 * A_BYTES + B_BYTES);
    }

    const int t    = threadIdx.x;
    const int lane = t & 31;
    const int wid  = t >> 5;
    const int wm   = wid & 1;
    const int wn   = wid >> 1;
    const int m0   = blockIdx.y * TBM;
    const int n0   = blockIdx.x * TBN;
    const int kofs = blockIdx.z * kslice_kt * TBK;

    float acc[4][8][4];
#pragma unroll
    for (int i = 0; i < 4; i++)
#pragma unroll
        for (int j = 0; j < 8; j++)
#pragma unroll
            for (int q = 0; q < 4; q++) acc[i][j][q] = 0.f;

    auto load_stage = [&](int s, int kt) {
        const int k0 = kofs + kt * TBK;
#pragma unroll
        for (int i = 0; i < 4; i++) {
            int idx = t + i * 128;
            int row = idx >> 2, seg = idx & 3;
            int so = row * ASTR + seg * 8;
            size_t go = (size_t)(m0 + row) * lda + k0 + seg * 8;
            cp16(&sAh[s][so], &Ah[go]);
            cp16(&sAl[s][so], &Al[go]);
        }
#pragma unroll
        for (int i = 0; i < 4; i++) {
            int idx = t + i * 128;
            int row = idx >> 4, seg = idx & 15;
            int so = row * BSTR + seg * 8;
            size_t go = (size_t)(k0 + row) * ldb + n0 + seg * 8;
            cp16(&sBh[s][so], &Bh[go]);
            if (NPROD == 3) cp16(&sBl[s][so], &Bl[go]);
        }
        asm volatile("cp.async.commit_group;\n");
    };

    load_stage(0, 0);
    if (KT > 1) load_stage(1, 1);

    int slot = 0;
    for (int kt = 0; kt < KT; kt++) {
        if (kt < KT - 1) asm volatile("cp.async.wait_group 1;\n" ::: "memory");
        else             asm volatile("cp.async.wait_group 0;\n" ::: "memory");
        __syncthreads();
        if (kt + 2 < KT) {
            int ns = slot + 2; if (ns >= NSTG) ns -= NSTG;
            load_stage(ns, kt + 2);
        }

#pragma unroll
        for (int ks = 0; ks < 2; ks++) {
            uint32_t afh[4][4], afl[4][4];
#pragma unroll
            for (int mt = 0; mt < 4; mt++) {
                int r = wm * 64 + mt * 16 + (lane & 15);
                int c = ks * 16 + ((lane >> 4) << 3);
                ldsm_x4(afh[mt], &sAh[slot][r * ASTR + c]);
                ldsm_x4(afl[mt], &sAl[slot][r * ASTR + c]);
            }
            uint32_t bfh[8][2], bfl[8][2];
#pragma unroll
            for (int np = 0; np < 4; np++) {
                int r = ks * 16 + (lane & 15);
                int c = wn * 64 + np * 16 + ((lane >> 4) << 3);
                uint32_t rh[4];
                ldsm_x4_t(rh, &sBh[slot][r * BSTR + c]);
                bfh[np * 2][0] = rh[0]; bfh[np * 2][1] = rh[1];
                bfh[np * 2 + 1][0] = rh[2]; bfh[np * 2 + 1][1] = rh[3];
                if (NPROD == 3) {
                    uint32_t rl[4];
                    ldsm_x4_t(rl, &sBl[slot][r * BSTR + c]);
                    bfl[np * 2][0] = rl[0]; bfl[np * 2][1] = rl[1];
                    bfl[np * 2 + 1][0] = rl[2]; bfl[np * 2 + 1][1] = rl[3];
                }
            }
#pragma unroll
            for (int mt = 0; mt < 4; mt++)
#pragma unroll
                for (int nt = 0; nt < 8; nt++) {
                    mma16816(acc[mt][nt], afh[mt], bfh[nt]);   // hh
                    mma16816(acc[mt][nt], afl[mt], bfh[nt]);   // lh
                    if (NPROD == 3)
                        mma16816(acc[mt][nt], afh[mt], bfl[nt]);  // hl
                }
        }
        slot++; if (slot >= NSTG) slot -= NSTG;
    }

    float* Cz = C + (size_t)blockIdx.z * ((size_t)BATCH * ldc);
#pragma unroll
    for (int mt = 0; mt < 4; mt++) {
#pragma unroll
        for (int nt = 0; nt < 8; nt++) {
            int col = n0 + wn * 64 + nt * 8 + (lane & 3) * 2;
            if (col >= Nreal) continue;
            float b0 = 0.f, b1 = 0.f;
            if (ACT != ACT_RAW) { b0 = bias[col]; b1 = bias[col + 1]; }
#pragma unroll
            for (int h = 0; h < 2; h++) {
                int row = m0 + wm * 64 + mt * 16 + (lane >> 2) + h * 8;
                float v0 = acc[mt][nt][2 * h + 0] + b0;
                float v1 = acc[mt][nt][2 * h + 1] + b1;
                if (ACT == ACT_TANH) { v0 = tanhf(v0); v1 = tanhf(v1); }
                *(float2*)&Cz[(size_t)row * ldc + col] = make_float2(v0, v1);
            }
        }
    }
}

// ---------------- split-K combine -> elu -> fp16 hi/lo ---------------------
template <int NS>
__global__ void reduce_elu_split(const float* __restrict__ ws, int ldw,
                                 const float* __restrict__ bias,
                                 __half* __restrict__ hi,
                                 __half* __restrict__ lo,
                                 int Nreal, int Npad, int total)
{
    int i = blockIdx.x * 256 + threadIdx.x;
    if (i >= total) return;
    int m = i / Npad, n = i - m * Npad;
    float v = 0.f;
    if (n < Nreal) {
        size_t o = (size_t)m * ldw + n;
        v = bias[n];
#pragma unroll
        for (int z = 0; z < NS; z++)
            v += ws[(size_t)z * BATCH * ldw + o];
        v = v > 0.f ? v : expm1f(v);
    }
    __half h = __float2half_rn(v);
    hi[i] = h;
    lo[i] = __float2half_rn(v - __half2float(h));
}

// ---------------- fused latent chain ----------------------------------------
// h2 = elu(sum_{z<3} ws2[z] + b2); logvar = h2@lw + lb; eps; triangular solve;
// g1 = elu(z @ dw1 + db1) emitted as fp16 hi/lo; last block writes Bmat.
__global__ void __launch_bounds__(256)
latent_chain_kernel(const float* __restrict__ ws2, int ldw,
                    const float* __restrict__ b2,
                    const float* __restrict__ lw, const float* __restrict__ lb,
                    const float* __restrict__ W,
                    const float* __restrict__ noise,
                    const float* __restrict__ dw1, const float* __restrict__ db1,
                    float* __restrict__ lv_o, float* __restrict__ z_o,
                    float* __restrict__ bz_o, float* __restrict__ bm_o,
                    __half* __restrict__ g1h, __half* __restrict__ g1l)
{
    if (blockIdx.x == gridDim.x - 1) {        // Bmat block
        int t = threadIdx.x;
        int i = t >> 4, j = t & 15;
        bm_o[t] = (j > i) ? W[t] * (float)(j - i) : 0.f;
        return;
    }

    const int lane = threadIdx.x & 31;
    const int b = blockIdx.x * 8 + (threadIdx.x >> 5);

    float acc[D];
#pragma unroll
    for (int j = 0; j < D; j++) acc[j] = 0.f;

#pragma unroll
    for (int tt = 0; tt < 10; tt++) {
        int k = lane + tt * 32;
        if (k < H2) {
            size_t o = (size_t)b * ldw + k;
            float hv = b2[k];
#pragma unroll
            for (int z = 0; z < 3; z++)
                hv += ws2[(size_t)z * BATCH * ldw + o];
            hv = hv > 0.f ? hv : expm1f(hv);
#pragma unroll
            for (int j4 = 0; j4 < 4; j4++) {
                float4 w = *(const float4*)&lw[(size_t)k * D + j4 * 4];
                acc[j4 * 4 + 0] = fmaf(hv, w.x, acc[j4 * 4 + 0]);
                acc[j4 * 4 + 1] = fmaf(hv, w.y, acc[j4 * 4 + 1]);
                acc[j4 * 4 + 2] = fmaf(hv, w.z, acc[j4 * 4 + 2]);
                acc[j4 * 4 + 3] = fmaf(hv, w.w, acc[j4 * 4 + 3]);
            }
        }
    }
#pragma unroll
    for (int off = 16; off > 0; off >>= 1)
#pragma unroll
        for (int j = 0; j < D; j++)
            acc[j] += __shfl_xor_sync(0xFFFFFFFF, acc[j], off);

#pragma unroll
    for (int j = 0; j < D; j++) acc[j] += lb[j];

    // all lanes now hold the full logvar vector -> replicate solve everywhere
    float eps[D], zz[D], bz[D];
#pragma unroll
    for (int j = 0; j < D; j++)
        eps[j] = expf(0.5f * acc[j]) * noise[(size_t)b * D + j];
#pragma unroll
    for (int j = 0; j < D; j++) {
        float s = 0.f;
#pragma unroll
        for (int i = 0; i < D; i++)
            if (i < j) s = fmaf(zz[i], W[i * D + j] * (float)(j - i), s);
        bz[j] = s;
        zz[j] = eps[j] + s;
    }
    if (lane < D) {
        lv_o[(size_t)b * D + lane] = acc[lane];
        z_o [(size_t)b * D + lane] = zz[lane];
        bz_o[(size_t)b * D + lane] = bz[lane];
    }

    // dec1: g1 = elu(z @ dw1 + db1), padded to H2K, fp16 hi/lo
#pragma unroll
    for (int tt = 0; tt < H2K / 32; tt++) {
        int c = lane + tt * 32;
        float v = 0.f;
        if (c < H2) {
            v = db1[c];
#pragma unroll
            for (int k = 0; k < D; k++)
                v = fmaf(zz[k], dw1[k * H2 + c], v);
            v = v > 0.f ? v : expm1f(v);
        }
        __half h = __float2half_rn(v);
        size_t o = (size_t)b * H2K + c;
        g1h[o] = h;
        g1l[o] = __float2half_rn(v - __half2float(h));
    }
}

// ---------------- launch -----------------------------------------------------
extern "C" void kernel_launch(void* const* d_in, const int* in_sizes, int n_in,
                              void* d_out, int out_size)
{
    (void)in_sizes; (void)n_in; (void)out_size;

    const float* x        = (const float*)d_in[0];
    const float* noise    = (const float*)d_in[1];
    const float* enc_w1   = (const float*)d_in[2];
    const float* enc_b1   = (const float*)d_in[3];
    const float* enc_w2   = (const float*)d_in[4];
    const float* enc_b2   = (const float*)d_in[5];
    const float* logvar_w = (const float*)d_in[6];
    const float* logvar_b = (const float*)d_in[7];
    const float* W        = (const float*)d_in[8];
    const float* dec_w1   = (const float*)d_in[9];
    const float* dec_b1   = (const float*)d_in[10];
    const float* dec_w2   = (const float*)d_in[11];
    const float* dec_b2   = (const float*)d_in[12];
    const float* dec_w3   = (const float*)d_in[13];
    const float* dec_b3   = (const float*)d_in[14];

    float* out  = (float*)d_out;
    float* z_o  = out;
    float* lv_o = out + BATCH * D;
    float* bz_o = out + 2 * BATCH * D;
    float* bm_o = out + 3 * BATCH * D;
    float* xh_o = out + 3 * BATCH * D + D * D;

    float* ws;
    cudaGetSymbolAddress((void**)&ws, g_ws);
    __half *xh, *xl, *w1h, *h1h, *h1l, *w2h, *w2l;
    __half *g1h, *g1l, *dw2h, *dw2l, *g2h, *g2l, *w3h, *w3l;
    cudaGetSymbolAddress((void**)&xh,   g_xh);
    cudaGetSymbolAddress((void**)&xl,   g_xl);
    cudaGetSymbolAddress((void**)&w1h,  g_w1h);
    cudaGetSymbolAddress((void**)&h1h,  g_h1h);
    cudaGetSymbolAddress((void**)&h1l,  g_h1l);
    cudaGetSymbolAddress((void**)&w2h,  g_w2h);
    cudaGetSymbolAddress((void**)&w2l,  g_w2l);
    cudaGetSymbolAddress((void**)&g1h,  g_g1h);
    cudaGetSymbolAddress((void**)&g1l,  g_g1l);
    cudaGetSymbolAddress((void**)&dw2h, g_dw2h);
    cudaGetSymbolAddress((void**)&dw2l, g_dw2l);
    cudaGetSymbolAddress((void**)&g2h,  g_g2h);
    cudaGetSymbolAddress((void**)&g2l,  g_g2l);
    cudaGetSymbolAddress((void**)&w3h,  g_w3h);
    cudaGetSymbolAddress((void**)&w3l,  g_w3l);

    cudaFuncSetAttribute((const void*)mma_gemm_big<ACT_RAW, 2>,
                         cudaFuncAttributeMaxDynamicSharedMemorySize, SMEM_BYTES);
    cudaFuncSetAttribute((const void*)mma_gemm_big<ACT_RAW, 3>,
                         cudaFuncAttributeMaxDynamicSharedMemorySize, SMEM_BYTES);
    cudaFuncSetAttribute((const void*)mma_gemm_big<ACT_TANH, 3>,
                         cudaFuncAttributeMaxDynamicSharedMemorySize, SMEM_BYTES);

    dim3 blk(256);

    // ---- operand prep
    split_half_v4<<<dim3(IMG / 1024, BATCH), blk>>>(x, xh, xl, BATCH, IMG, IMG);
    conv_half_v4<<<dim3(1, IMG), blk>>>(enc_w1, w1h, IMG, H1, W1N);
    split_half_v4<<<dim3(1, H1K), blk>>>(enc_w2, w2h, w2l, H1, H2, H2N);
    split_half_v4<<<dim3(1, H2K), blk>>>(dec_w2, dw2h, dw2l, H2, H2, H2N);
    split_half_v4<<<dim3(IMG / 1024, H2K), blk>>>(dec_w3, w3h, w3l, H2, IMG, IMG);

    // ---- enc1: 2-product, split-K=4
    {
        int kt = IMG / (4 * TBK);                 // 216
        mma_gemm_big<ACT_RAW, 2><<<dim3(W1N / TBN, BATCH / TBM, 4), 128, SMEM_BYTES>>>(
            xh, xl, IMG, w1h, nullptr, W1N, nullptr, ws, W1N, W1N, kt, kt);
    }
    reduce_elu_split<4><<<(BATCH * H1K + 255) / 256, blk>>>(
        ws, W1N, enc_b1, h1h, h1l, H1, H1K, BATCH * H1K);

    // ---- enc2: 3-product, 3 K-slices of 10 kt
    mma_gemm_big<ACT_RAW, 3><<<dim3(H2N / TBN, BATCH / TBM, 3), 128, SMEM_BYTES>>>(
        h1h, h1l, H1K, w2h, w2l, H2N, nullptr, ws, H2N, H2N, 10, 10);

    // ---- fused latent chain (h2 sum + logvar + solve + dec1 + Bmat)
    latent_chain_kernel<<<BATCH / 8 + 1, blk>>>(
        ws, H2N, enc_b2, logvar_w, logvar_b, W, noise, dec_w1, dec_b1,
        lv_o, z_o, bz_o, bm_o, g1h, g1l);

    // ---- dec2: 3-product, 2 K-slices of 5 kt
    mma_gemm_big<ACT_RAW, 3><<<dim3(H2N / TBN, BATCH / TBM, 2), 128, SMEM_BYTES>>>(
        g1h, g1l, H2K, dw2h, dw2l, H2N, nullptr, ws, H2N, H2N, 5, 5);
    reduce_elu_split<2><<<(BATCH * H2K + 255) / 256, blk>>>(
        ws, H2N, dec_b2, g2h, g2l, H2, H2K, BATCH * H2K);

    // ---- dec3: 3-product, tanh
    mma_gemm_big<ACT_TANH, 3><<<dim3(IMG / TBN, BATCH / TBM, 1), 128, SMEM_BYTES>>>(
        g2h, g2l, H2K, w3h, w3l, IMG, dec_b3, xh_o, IMG, IMG, H2K / TBK, H2K / TBK);
}